// round 1
// baseline (speedup 1.0000x reference)
#include <cuda_runtime.h>
#include <cuda_bf16.h>
#include <math.h>

// Problem constants
#define SLEN 2048
#define DIN  2048
#define NH   32
#define NKV  8
#define HD   64
#define DOUT 2048   // NH*HD
#define KVD  512    // NKV*HD

// ---------------- scratch (device globals; no allocs allowed) ----------------
__device__ float g_qraw[SLEN * DOUT];   // [s][h*64+d]
__device__ float g_kraw[SLEN * KVD];    // [s][kv*64+d]
__device__ float g_vraw[SLEN * KVD];
__device__ float g_q[NH * SLEN * HD];   // [h][s][d]  (post norm+rope)
__device__ float g_k[NKV * SLEN * HD];  // [kv][s][d]
__device__ float g_v[NKV * SLEN * HD];  // [kv][s][d]
__device__ float g_ctx[SLEN * DOUT];    // [s][h*64+d]

// ---------------- generic SGEMM body: C[M,N] = A[M,K] @ B[K,N] ----------------
// 128x128 block, BK=8, 8x8 per thread, 256 threads.
#define BM 128
#define BN 128
#define BK 8
#define TM 8
#define TN 8

__device__ __forceinline__ void gemm_body(const float* __restrict__ A,
                                          const float* __restrict__ B,
                                          float* __restrict__ C,
                                          int M, int N, int K)
{
    __shared__ float As[BK][BM];
    __shared__ float Bs[BK][BN];
    const int tid = threadIdx.x;
    const int tx = tid & 15;
    const int ty = tid >> 4;
    const int bm = blockIdx.y * BM;
    const int bn = blockIdx.x * BN;

    float acc[TM][TN];
#pragma unroll
    for (int i = 0; i < TM; i++)
#pragma unroll
        for (int j = 0; j < TN; j++) acc[i][j] = 0.f;

    const int arow = tid >> 1;        // 0..127
    const int acol = (tid & 1) * 4;   // 0 or 4
    const int brow = tid >> 5;        // 0..7
    const int bcol = (tid & 31) * 4;  // 0..124

    const float* Aptr = A + (size_t)(bm + arow) * K + acol;
    const float* Bptr = B + (size_t)brow * N + bn + bcol;

    for (int k0 = 0; k0 < K; k0 += BK) {
        float4 av = *reinterpret_cast<const float4*>(Aptr + k0);
        float4 bv = *reinterpret_cast<const float4*>(Bptr + (size_t)k0 * N);
        As[acol + 0][arow] = av.x;
        As[acol + 1][arow] = av.y;
        As[acol + 2][arow] = av.z;
        As[acol + 3][arow] = av.w;
        *reinterpret_cast<float4*>(&Bs[brow][bcol]) = bv;
        __syncthreads();
#pragma unroll
        for (int kk = 0; kk < BK; kk++) {
            float ra[TM], rb[TN];
#pragma unroll
            for (int i = 0; i < TM; i++) ra[i] = As[kk][ty * TM + i];
#pragma unroll
            for (int j = 0; j < TN; j++) rb[j] = Bs[kk][tx * TN + j];
#pragma unroll
            for (int i = 0; i < TM; i++)
#pragma unroll
                for (int j = 0; j < TN; j++)
                    acc[i][j] += ra[i] * rb[j];
        }
        __syncthreads();
    }
#pragma unroll
    for (int i = 0; i < TM; i++) {
        float* crow = C + (size_t)(bm + ty * TM + i) * N + bn + tx * TN;
#pragma unroll
        for (int j = 0; j < TN; j += 4) {
            float4 v = make_float4(acc[i][j], acc[i][j + 1], acc[i][j + 2], acc[i][j + 3]);
            *reinterpret_cast<float4*>(crow + j) = v;
        }
    }
}

__global__ __launch_bounds__(256) void k_qproj(const float* __restrict__ x,
                                               const float* __restrict__ Wq)
{
    gemm_body(x, Wq, g_qraw, SLEN, DOUT, DIN);
}

__global__ __launch_bounds__(256) void k_kvproj(const float* __restrict__ x,
                                                const float* __restrict__ Wk,
                                                const float* __restrict__ Wv)
{
    const float* B = blockIdx.z ? Wv : Wk;
    float* C = blockIdx.z ? g_vraw : g_kraw;
    gemm_body(x, B, C, SLEN, KVD, DIN);
}

__global__ __launch_bounds__(256) void k_oproj(const float* __restrict__ Wo,
                                               float* __restrict__ out)
{
    gemm_body(g_ctx, Wo, out, SLEN, DIN, DOUT);
}

// ---------------- RMSNorm + RoPE + layout transform ----------------
// grid (S, 48): y<32 -> q head, 32..39 -> k head, 40..47 -> v copy. block = 64.
__global__ void normrope_kernel(const float* __restrict__ cosb,
                                const float* __restrict__ sinb,
                                const float* __restrict__ qw,
                                const float* __restrict__ kw)
{
    const int s = blockIdx.x;
    const int u = blockIdx.y;
    const int d = threadIdx.x;  // 0..63
    __shared__ float sh[64];
    __shared__ float ssum[2];

    if (u < 40) {
        float val;
        const float* w;
        if (u < 32) { val = g_qraw[(size_t)s * DOUT + u * 64 + d]; w = qw; }
        else        { val = g_kraw[(size_t)s * KVD + (u - 32) * 64 + d]; w = kw; }
        float sq = val * val;
#pragma unroll
        for (int mk = 16; mk; mk >>= 1) sq += __shfl_xor_sync(0xffffffffu, sq, mk);
        if ((d & 31) == 0) ssum[d >> 5] = sq;
        __syncthreads();
        float tot = ssum[0] + ssum[1];
        float xn = val * rsqrtf(tot * (1.0f / 64.0f) + 1e-6f) * w[d];
        sh[d] = xn;
        __syncthreads();
        float rot = (d < 32) ? -sh[d + 32] : sh[d - 32];
        float o = xn * cosb[s * 64 + d] + rot * sinb[s * 64 + d];
        if (u < 32) g_q[((size_t)u * SLEN + s) * 64 + d] = o;
        else        g_k[((size_t)(u - 32) * SLEN + s) * 64 + d] = o;
    } else {
        int kv = u - 40;
        g_v[((size_t)kv * SLEN + s) * 64 + d] = g_vraw[(size_t)s * KVD + kv * 64 + d];
    }
}

// ---------------- Flash attention (causal, GQA) ----------------
// grid (32 heads, 32 q-blocks), 256 threads. BM=BN=HD=64.
// smem: Qt[d][r], V[t][d], KP = Kt[d][t] aliased with Pt[t][r].  48KB total.
__global__ __launch_bounds__(256) void attn_kernel()
{
    __shared__ float sQt[64 * 64];
    __shared__ float sV [64 * 64];
    __shared__ float sKP[64 * 64];

    const int tid = threadIdx.x;
    const int tx = tid & 15;
    const int ty = tid >> 4;
    const int h = blockIdx.x;
    const int qb = 31 - (int)blockIdx.y;   // heavy (long) blocks first
    const int s0 = qb * 64;
    const int kvh = h >> 2;

    const float* Qg = g_q + ((size_t)h * SLEN + s0) * 64;
    const float* Kg = g_k + (size_t)kvh * SLEN * 64;
    const float* Vg = g_v + (size_t)kvh * SLEN * 64;

    // Load Q tile transposed: sQt[d][r]
    {
        const int r = tid >> 2;
        const int c0 = (tid & 3) * 16;
#pragma unroll
        for (int j = 0; j < 16; j += 4) {
            float4 v = *reinterpret_cast<const float4*>(Qg + r * 64 + c0 + j);
            sQt[(c0 + j + 0) * 64 + r] = v.x;
            sQt[(c0 + j + 1) * 64 + r] = v.y;
            sQt[(c0 + j + 2) * 64 + r] = v.z;
            sQt[(c0 + j + 3) * 64 + r] = v.w;
        }
    }

    float m[4], l[4], acc[4][4];
#pragma unroll
    for (int i = 0; i < 4; i++) {
        m[i] = -1e30f;
        l[i] = 0.f;
#pragma unroll
        for (int j = 0; j < 4; j++) acc[i][j] = 0.f;
    }

    const float scale = 0.125f;  // 1/sqrt(64)

    for (int kb = 0; kb <= qb; kb++) {
        const int t0 = kb * 64;
        __syncthreads();  // prev PV reads done (and Q load on first iter)

        // Load K transposed (sKP[d][t]) + V natural (sV[t][d])
        {
            const int r = tid >> 2;
            const int c0 = (tid & 3) * 16;
#pragma unroll
            for (int j = 0; j < 16; j += 4) {
                float4 kv4 = *reinterpret_cast<const float4*>(Kg + (size_t)(t0 + r) * 64 + c0 + j);
                sKP[(c0 + j + 0) * 64 + r] = kv4.x;
                sKP[(c0 + j + 1) * 64 + r] = kv4.y;
                sKP[(c0 + j + 2) * 64 + r] = kv4.z;
                sKP[(c0 + j + 3) * 64 + r] = kv4.w;
                float4 vv = *reinterpret_cast<const float4*>(Vg + (size_t)(t0 + r) * 64 + c0 + j);
                *reinterpret_cast<float4*>(&sV[r * 64 + c0 + j]) = vv;
            }
        }
        __syncthreads();

        // scores: sreg[i][j] = sum_d Qt[d][ty*4+i] * Kt[d][tx*4+j]
        float sreg[4][4];
#pragma unroll
        for (int i = 0; i < 4; i++)
#pragma unroll
            for (int j = 0; j < 4; j++) sreg[i][j] = 0.f;

#pragma unroll 8
        for (int d = 0; d < 64; d++) {
            float4 qv = *reinterpret_cast<const float4*>(&sQt[d * 64 + ty * 4]);
            float4 kv4 = *reinterpret_cast<const float4*>(&sKP[d * 64 + tx * 4]);
            float qa[4] = {qv.x, qv.y, qv.z, qv.w};
            float ka[4] = {kv4.x, kv4.y, kv4.z, kv4.w};
#pragma unroll
            for (int i = 0; i < 4; i++)
#pragma unroll
                for (int j = 0; j < 4; j++)
                    sreg[i][j] += qa[i] * ka[j];
        }

#pragma unroll
        for (int i = 0; i < 4; i++)
#pragma unroll
            for (int j = 0; j < 4; j++) sreg[i][j] *= scale;

        if (kb == qb) {  // diagonal block: causal mask t > s
#pragma unroll
            for (int i = 0; i < 4; i++) {
                const int r = ty * 4 + i;
#pragma unroll
                for (int j = 0; j < 4; j++) {
                    if (tx * 4 + j > r) sreg[i][j] = -1e30f;
                }
            }
        }

        // online softmax update (row r handled by 16 lanes sharing ty)
#pragma unroll
        for (int i = 0; i < 4; i++) {
            float mx = fmaxf(fmaxf(sreg[i][0], sreg[i][1]), fmaxf(sreg[i][2], sreg[i][3]));
#pragma unroll
            for (int mk = 8; mk; mk >>= 1) mx = fmaxf(mx, __shfl_xor_sync(0xffffffffu, mx, mk));
            float mi = fmaxf(m[i], mx);
            float corr = __expf(m[i] - mi);
            m[i] = mi;
            float rs = 0.f;
#pragma unroll
            for (int j = 0; j < 4; j++) {
                float p = __expf(sreg[i][j] - mi);
                sreg[i][j] = p;
                rs += p;
            }
#pragma unroll
            for (int mk = 8; mk; mk >>= 1) rs += __shfl_xor_sync(0xffffffffu, rs, mk);
            l[i] = l[i] * corr + rs;
#pragma unroll
            for (int j = 0; j < 4; j++) acc[i][j] *= corr;
        }

        __syncthreads();  // Kt reads complete before overwriting with Pt

        // write Pt[t][r]
#pragma unroll
        for (int j = 0; j < 4; j++)
#pragma unroll
            for (int i = 0; i < 4; i++)
                sKP[(tx * 4 + j) * 64 + ty * 4 + i] = sreg[i][j];
        __syncthreads();

        // PV: acc[i][j] += sum_t Pt[t][ty*4+i] * V[t][tx*4+j]
#pragma unroll 8
        for (int t = 0; t < 64; t++) {
            float4 pv = *reinterpret_cast<const float4*>(&sKP[t * 64 + ty * 4]);
            float4 vv = *reinterpret_cast<const float4*>(&sV[t * 64 + tx * 4]);
            float pa[4] = {pv.x, pv.y, pv.z, pv.w};
            float va[4] = {vv.x, vv.y, vv.z, vv.w};
#pragma unroll
            for (int i = 0; i < 4; i++)
#pragma unroll
                for (int j = 0; j < 4; j++)
                    acc[i][j] += pa[i] * va[j];
        }
    }

    // epilogue: normalize and write ctx[s][h*64+d]
#pragma unroll
    for (int i = 0; i < 4; i++) {
        const float inv = 1.0f / l[i];
        const int r = s0 + ty * 4 + i;
        float4 o = make_float4(acc[i][0] * inv, acc[i][1] * inv, acc[i][2] * inv, acc[i][3] * inv);
        *reinterpret_cast<float4*>(&g_ctx[(size_t)r * DOUT + h * 64 + tx * 4]) = o;
    }
}

// ---------------- launch ----------------
extern "C" void kernel_launch(void* const* d_in, const int* in_sizes, int n_in,
                              void* d_out, int out_size)
{
    const float* x    = (const float*)d_in[0];
    // d_in[1] = mask (causal triu, implemented analytically) -- unused
    const float* cosb = (const float*)d_in[2];
    const float* sinb = (const float*)d_in[3];
    const float* Wq   = (const float*)d_in[4];
    const float* Wk   = (const float*)d_in[5];
    const float* Wv   = (const float*)d_in[6];
    const float* Wo   = (const float*)d_in[7];
    const float* qw   = (const float*)d_in[8];
    const float* kw   = (const float*)d_in[9];
    float* out = (float*)d_out;

    (void)in_sizes; (void)n_in; (void)out_size;

    dim3 gq(DOUT / BN, SLEN / BM);       // (16,16)
    k_qproj<<<gq, 256>>>(x, Wq);

    dim3 gkv(KVD / BN, SLEN / BM, 2);    // (4,16,2)
    k_kvproj<<<gkv, 256>>>(x, Wk, Wv);

    normrope_kernel<<<dim3(SLEN, 48), 64>>>(cosb, sinb, qw, kw);

    attn_kernel<<<dim3(NH, SLEN / 64), 256>>>();

    dim3 go(DIN / BN, SLEN / BM);        // (16,16)
    k_oproj<<<go, 256>>>(Wo, out);
}

// round 3
// speedup vs baseline: 1.6040x; 1.6040x over previous
#include <cuda_runtime.h>
#include <cuda_bf16.h>
#include <math.h>
#include <stdint.h>

// Problem constants
#define SLEN 2048
#define DIN  2048
#define NH   32
#define NKV  8
#define HD   64
#define DOUT 2048   // NH*HD
#define KVD  512    // NKV*HD

// ---------------- scratch (device globals; no allocs allowed) ----------------
__device__ float g_qraw[SLEN * DOUT];   // [s][h*64+d]
__device__ float g_kraw[SLEN * KVD];    // [s][kv*64+d]
__device__ float g_vraw[SLEN * KVD];
__device__ float g_q[NH * SLEN * HD];   // [h][s][d]  (post norm+rope)
__device__ float g_k[NKV * SLEN * HD];  // [kv][s][d]
__device__ float g_v[NKV * SLEN * HD];  // [kv][s][d]
__device__ float g_ctx[SLEN * DOUT];    // [s][h*64+d]

// bf16 split operands (A activations row-major [M][K]; weights transposed [N][K])
__device__ __align__(256) __nv_bfloat16 g_xh[SLEN * DIN];
__device__ __align__(256) __nv_bfloat16 g_xl[SLEN * DIN];
__device__ __align__(256) __nv_bfloat16 g_wqh[DOUT * DIN];
__device__ __align__(256) __nv_bfloat16 g_wql[DOUT * DIN];
__device__ __align__(256) __nv_bfloat16 g_wkh[KVD * DIN];
__device__ __align__(256) __nv_bfloat16 g_wkl[KVD * DIN];
__device__ __align__(256) __nv_bfloat16 g_wvh[KVD * DIN];
__device__ __align__(256) __nv_bfloat16 g_wvl[KVD * DIN];
__device__ __align__(256) __nv_bfloat16 g_woh[DIN * DOUT];
__device__ __align__(256) __nv_bfloat16 g_wol[DIN * DOUT];
__device__ __align__(256) __nv_bfloat16 g_ch[SLEN * DOUT];
__device__ __align__(256) __nv_bfloat16 g_cl[SLEN * DOUT];

// ---------------- PTX helpers ----------------
__device__ __forceinline__ uint32_t smem_u32(const void* p) {
    uint32_t a;
    asm("{ .reg .u64 t; cvta.to.shared.u64 t, %1; cvt.u32.u64 %0, t; }" : "=r"(a) : "l"(p));
    return a;
}

#define CP_ASYNC16(dst, src) \
    asm volatile("cp.async.cg.shared.global [%0], [%1], 16;" :: "r"(dst), "l"(src) : "memory")
#define CP_COMMIT() asm volatile("cp.async.commit_group;" ::: "memory")
#define CP_WAIT0()  asm volatile("cp.async.wait_group 0;" ::: "memory")
#define CP_WAIT1()  asm volatile("cp.async.wait_group 1;" ::: "memory")

__device__ __forceinline__ void ldsm_x4(uint32_t* r, uint32_t addr) {
    asm volatile("ldmatrix.sync.aligned.m8n8.x4.shared.b16 {%0,%1,%2,%3}, [%4];"
                 : "=r"(r[0]), "=r"(r[1]), "=r"(r[2]), "=r"(r[3]) : "r"(addr));
}
__device__ __forceinline__ void ldsm_x2(uint32_t* r, uint32_t addr) {
    asm volatile("ldmatrix.sync.aligned.m8n8.x2.shared.b16 {%0,%1}, [%2];"
                 : "=r"(r[0]), "=r"(r[1]) : "r"(addr));
}
__device__ __forceinline__ void mma16816(float* c, const uint32_t* a, const uint32_t* b) {
    asm volatile("mma.sync.aligned.m16n8k16.row.col.f32.bf16.bf16.f32 "
                 "{%0,%1,%2,%3}, {%4,%5,%6,%7}, {%8,%9}, {%0,%1,%2,%3};"
                 : "+f"(c[0]), "+f"(c[1]), "+f"(c[2]), "+f"(c[3])
                 : "r"(a[0]), "r"(a[1]), "r"(a[2]), "r"(a[3]), "r"(b[0]), "r"(b[1]));
}

// ---------------- HMMA split-bf16 GEMM: C[M,N] = A[M,K] @ (Bt[N,K])^T ----------------
// CTA 128x128, BK=32, 256 threads (8 warps as 2x4), 4x4 m16n8k16 tiles per warp.
// smem rows padded to 80B -> conflict-free ldmatrix.
#define GBK 32
#define LSTR 40                         // bf16 per smem row (32 + 8 pad)
#define TILE_B (128 * LSTR * 2)         // 10240 bytes
#define STAGE_B (4 * TILE_B)            // Ah, Al, Bh, Bl
#define GEMM_SMEM (2 * STAGE_B)         // 81920

__device__ __forceinline__ void load_stage(uint32_t stage,
                                           const __nv_bfloat16* __restrict__ Ah,
                                           const __nv_bfloat16* __restrict__ Al,
                                           const __nv_bfloat16* __restrict__ Bh,
                                           const __nv_bfloat16* __restrict__ Bl,
                                           int K, int k0, int tid)
{
    const __nv_bfloat16* tp[4] = {Ah, Al, Bh, Bl};
#pragma unroll
    for (int t = 0; t < 4; t++) {
        const char* src_base = (const char*)tp[t] + (size_t)k0 * 2;
        uint32_t dtile = stage + t * TILE_B;
#pragma unroll
        for (int it = 0; it < 2; it++) {
            int u = tid + it * 256;          // 0..511
            int row = u >> 2;
            int ch = (u & 3) * 16;
            CP_ASYNC16(dtile + row * 80 + ch, src_base + (size_t)row * K * 2 + ch);
        }
    }
    CP_COMMIT();
}

__device__ __forceinline__ void hmma_gemm_body(const __nv_bfloat16* __restrict__ Ah,
                                               const __nv_bfloat16* __restrict__ Al,
                                               const __nv_bfloat16* __restrict__ Bh,
                                               const __nv_bfloat16* __restrict__ Bl,
                                               float* __restrict__ C, int K, int ldc)
{
    extern __shared__ char smem[];
    const uint32_t sb = smem_u32(smem);
    const int tid = threadIdx.x;
    const int wid = tid >> 5;
    const int lane = tid & 31;
    const int gm0 = blockIdx.y * 128;
    const int gn0 = blockIdx.x * 128;
    const int warpM = (wid >> 2) * 64;
    const int warpN = (wid & 3) * 32;
    const int NC = K / GBK;

    const __nv_bfloat16* Ah0 = Ah + (size_t)gm0 * K;
    const __nv_bfloat16* Al0 = Al + (size_t)gm0 * K;
    const __nv_bfloat16* Bh0 = Bh + (size_t)gn0 * K;
    const __nv_bfloat16* Bl0 = Bl + (size_t)gn0 * K;

    float acc[4][4][4];
#pragma unroll
    for (int i = 0; i < 4; i++)
#pragma unroll
        for (int j = 0; j < 4; j++)
#pragma unroll
            for (int v = 0; v < 4; v++) acc[i][j][v] = 0.f;

    // A frag byte offsets within a tile
    const int arow = lane & 15;
    const int acol = (lane >> 4) << 3;      // 0 or 8 (bf16)
    const int brow = lane & 7;
    const int bcol = ((lane >> 3) & 1) << 3;

    load_stage(sb, Ah0, Al0, Bh0, Bl0, K, 0, tid);

    for (int c = 0; c < NC; c++) {
        if (c + 1 < NC) {
            load_stage(sb + ((c + 1) & 1) * STAGE_B, Ah0, Al0, Bh0, Bl0, K, (c + 1) * GBK, tid);
            CP_WAIT1();
        } else {
            CP_WAIT0();
        }
        __syncthreads();

        const uint32_t base = sb + (c & 1) * STAGE_B;
#pragma unroll
        for (int kk = 0; kk < 32; kk += 16) {
            uint32_t aH[4][4], aL[4][4], bH[4][2], bL[4][2];
#pragma unroll
            for (int mi = 0; mi < 4; mi++) {
                uint32_t ao = (uint32_t)((warpM + mi * 16 + arow) * 80 + (kk + acol) * 2);
                ldsm_x4(aH[mi], base + 0 * TILE_B + ao);
                ldsm_x4(aL[mi], base + 1 * TILE_B + ao);
            }
#pragma unroll
            for (int nj = 0; nj < 4; nj++) {
                uint32_t bo = (uint32_t)((warpN + nj * 8 + brow) * 80 + (kk + bcol) * 2);
                ldsm_x2(bH[nj], base + 2 * TILE_B + bo);
                ldsm_x2(bL[nj], base + 3 * TILE_B + bo);
            }
#pragma unroll
            for (int mi = 0; mi < 4; mi++)
#pragma unroll
                for (int nj = 0; nj < 4; nj++) {
                    mma16816(acc[mi][nj], aH[mi], bH[nj]);
                    mma16816(acc[mi][nj], aL[mi], bH[nj]);
                    mma16816(acc[mi][nj], aH[mi], bL[nj]);
                }
        }
        __syncthreads();
    }

    // epilogue: c0,c1 at (row, col), c2,c3 at (row+8, col)
    const int r0 = lane >> 2;
    const int c0 = (lane & 3) * 2;
#pragma unroll
    for (int mi = 0; mi < 4; mi++)
#pragma unroll
        for (int nj = 0; nj < 4; nj++) {
            float* cp = C + (size_t)(gm0 + warpM + mi * 16 + r0) * ldc + gn0 + warpN + nj * 8 + c0;
            *reinterpret_cast<float2*>(cp) = make_float2(acc[mi][nj][0], acc[mi][nj][1]);
            *reinterpret_cast<float2*>(cp + 8 * ldc) = make_float2(acc[mi][nj][2], acc[mi][nj][3]);
        }
}

__global__ __launch_bounds__(256, 1) void gemm_q_kernel() {
    hmma_gemm_body(g_xh, g_xl, g_wqh, g_wql, g_qraw, DIN, DOUT);
}
__global__ __launch_bounds__(256, 1) void gemm_kv_kernel() {
    if (blockIdx.z == 0) hmma_gemm_body(g_xh, g_xl, g_wkh, g_wkl, g_kraw, DIN, KVD);
    else                 hmma_gemm_body(g_xh, g_xl, g_wvh, g_wvl, g_vraw, DIN, KVD);
}
__global__ __launch_bounds__(256, 1) void gemm_o_kernel(float* __restrict__ out) {
    hmma_gemm_body(g_ch, g_cl, g_woh, g_wol, out, DOUT, DIN);
}

// ---------------- converts ----------------
__global__ void xconv_kernel(const float* __restrict__ x) {
    int i = blockIdx.x * 256 + threadIdx.x;
    float v = x[i];
    __nv_bfloat16 h = __float2bfloat16(v);
    g_xh[i] = h;
    g_xl[i] = __float2bfloat16(v - __bfloat162float(h));
}
__global__ void ctxconv_kernel() {
    int i = blockIdx.x * 256 + threadIdx.x;
    float v = g_ctx[i];
    __nv_bfloat16 h = __float2bfloat16(v);
    g_ch[i] = h;
    g_cl[i] = __float2bfloat16(v - __bfloat162float(h));
}

// transpose + split: W[R][Cc] -> Bt[c][r] (hi/lo)
__device__ __forceinline__ void wconv_body(const float* __restrict__ W,
                                           __nv_bfloat16* __restrict__ Bh,
                                           __nv_bfloat16* __restrict__ Bl,
                                           int R, int Cc)
{
    __shared__ float t[32][33];
    const int c0 = blockIdx.x * 32;
    const int r0 = blockIdx.y * 32;
    const int tx = threadIdx.x;
    const int ty = threadIdx.y;
#pragma unroll
    for (int i = ty; i < 32; i += 8)
        t[i][tx] = W[(size_t)(r0 + i) * Cc + c0 + tx];
    __syncthreads();
#pragma unroll
    for (int i = ty; i < 32; i += 8) {
        float v = t[tx][i];                   // = W[r0+tx][c0+i]
        size_t o = (size_t)(c0 + i) * R + r0 + tx;
        __nv_bfloat16 h = __float2bfloat16(v);
        Bh[o] = h;
        Bl[o] = __float2bfloat16(v - __bfloat162float(h));
    }
}
__global__ void wconv_q(const float* __restrict__ W) { wconv_body(W, g_wqh, g_wql, DIN, DOUT); }
__global__ void wconv_k(const float* __restrict__ W) { wconv_body(W, g_wkh, g_wkl, DIN, KVD); }
__global__ void wconv_v(const float* __restrict__ W) { wconv_body(W, g_wvh, g_wvl, DIN, KVD); }
__global__ void wconv_o(const float* __restrict__ W) { wconv_body(W, g_woh, g_wol, DOUT, DIN); }

// ---------------- RMSNorm + RoPE + layout transform ----------------
__global__ void normrope_kernel(const float* __restrict__ cosb,
                                const float* __restrict__ sinb,
                                const float* __restrict__ qw,
                                const float* __restrict__ kw)
{
    const int s = blockIdx.x;
    const int u = blockIdx.y;
    const int d = threadIdx.x;  // 0..63
    __shared__ float sh[64];
    __shared__ float ssum[2];

    if (u < 40) {
        float val;
        const float* w;
        if (u < 32) { val = g_qraw[(size_t)s * DOUT + u * 64 + d]; w = qw; }
        else        { val = g_kraw[(size_t)s * KVD + (u - 32) * 64 + d]; w = kw; }
        float sq = val * val;
#pragma unroll
        for (int mk = 16; mk; mk >>= 1) sq += __shfl_xor_sync(0xffffffffu, sq, mk);
        if ((d & 31) == 0) ssum[d >> 5] = sq;
        __syncthreads();
        float tot = ssum[0] + ssum[1];
        float xn = val * rsqrtf(tot * (1.0f / 64.0f) + 1e-6f) * w[d];
        sh[d] = xn;
        __syncthreads();
        float rot = (d < 32) ? -sh[d + 32] : sh[d - 32];
        float o = xn * cosb[s * 64 + d] + rot * sinb[s * 64 + d];
        if (u < 32) g_q[((size_t)u * SLEN + s) * 64 + d] = o;
        else        g_k[((size_t)(u - 32) * SLEN + s) * 64 + d] = o;
    } else {
        int kv = u - 40;
        g_v[((size_t)kv * SLEN + s) * 64 + d] = g_vraw[(size_t)s * KVD + kv * 64 + d];
    }
}

// ---------------- Flash attention (causal, GQA) ----------------
__global__ __launch_bounds__(256) void attn_kernel()
{
    __shared__ float sQt[64 * 64];
    __shared__ float sV [64 * 64];
    __shared__ float sKP[64 * 64];

    const int tid = threadIdx.x;
    const int tx = tid & 15;
    const int ty = tid >> 4;
    const int h = blockIdx.x;
    const int qb = 31 - (int)blockIdx.y;   // heavy blocks first
    const int s0 = qb * 64;
    const int kvh = h >> 2;

    const float* Qg = g_q + ((size_t)h * SLEN + s0) * 64;
    const float* Kg = g_k + (size_t)kvh * SLEN * 64;
    const float* Vg = g_v + (size_t)kvh * SLEN * 64;

    {
        const int r = tid >> 2;
        const int c0 = (tid & 3) * 16;
#pragma unroll
        for (int j = 0; j < 16; j += 4) {
            float4 v = *reinterpret_cast<const float4*>(Qg + r * 64 + c0 + j);
            sQt[(c0 + j + 0) * 64 + r] = v.x;
            sQt[(c0 + j + 1) * 64 + r] = v.y;
            sQt[(c0 + j + 2) * 64 + r] = v.z;
            sQt[(c0 + j + 3) * 64 + r] = v.w;
        }
    }

    float m[4], l[4], acc[4][4];
#pragma unroll
    for (int i = 0; i < 4; i++) {
        m[i] = -1e30f;
        l[i] = 0.f;
#pragma unroll
        for (int j = 0; j < 4; j++) acc[i][j] = 0.f;
    }

    const float scale = 0.125f;

    for (int kb = 0; kb <= qb; kb++) {
        const int t0 = kb * 64;
        __syncthreads();

        {
            const int r = tid >> 2;
            const int c0 = (tid & 3) * 16;
#pragma unroll
            for (int j = 0; j < 16; j += 4) {
                float4 kv4 = *reinterpret_cast<const float4*>(Kg + (size_t)(t0 + r) * 64 + c0 + j);
                sKP[(c0 + j + 0) * 64 + r] = kv4.x;
                sKP[(c0 + j + 1) * 64 + r] = kv4.y;
                sKP[(c0 + j + 2) * 64 + r] = kv4.z;
                sKP[(c0 + j + 3) * 64 + r] = kv4.w;
                float4 vv = *reinterpret_cast<const float4*>(Vg + (size_t)(t0 + r) * 64 + c0 + j);
                *reinterpret_cast<float4*>(&sV[r * 64 + c0 + j]) = vv;
            }
        }
        __syncthreads();

        float sreg[4][4];
#pragma unroll
        for (int i = 0; i < 4; i++)
#pragma unroll
            for (int j = 0; j < 4; j++) sreg[i][j] = 0.f;

#pragma unroll 8
        for (int d = 0; d < 64; d++) {
            float4 qv = *reinterpret_cast<const float4*>(&sQt[d * 64 + ty * 4]);
            float4 kv4 = *reinterpret_cast<const float4*>(&sKP[d * 64 + tx * 4]);
            float qa[4] = {qv.x, qv.y, qv.z, qv.w};
            float ka[4] = {kv4.x, kv4.y, kv4.z, kv4.w};
#pragma unroll
            for (int i = 0; i < 4; i++)
#pragma unroll
                for (int j = 0; j < 4; j++)
                    sreg[i][j] += qa[i] * ka[j];
        }

#pragma unroll
        for (int i = 0; i < 4; i++)
#pragma unroll
            for (int j = 0; j < 4; j++) sreg[i][j] *= scale;

        if (kb == qb) {
#pragma unroll
            for (int i = 0; i < 4; i++) {
                const int r = ty * 4 + i;
#pragma unroll
                for (int j = 0; j < 4; j++) {
                    if (tx * 4 + j > r) sreg[i][j] = -1e30f;
                }
            }
        }

#pragma unroll
        for (int i = 0; i < 4; i++) {
            float mx = fmaxf(fmaxf(sreg[i][0], sreg[i][1]), fmaxf(sreg[i][2], sreg[i][3]));
#pragma unroll
            for (int mk = 8; mk; mk >>= 1) mx = fmaxf(mx, __shfl_xor_sync(0xffffffffu, mx, mk));
            float mi = fmaxf(m[i], mx);
            float corr = __expf(m[i] - mi);
            m[i] = mi;
            float rs = 0.f;
#pragma unroll
            for (int j = 0; j < 4; j++) {
                float p = __expf(sreg[i][j] - mi);
                sreg[i][j] = p;
                rs += p;
            }
#pragma unroll
            for (int mk = 8; mk; mk >>= 1) rs += __shfl_xor_sync(0xffffffffu, rs, mk);
            l[i] = l[i] * corr + rs;
#pragma unroll
            for (int j = 0; j < 4; j++) acc[i][j] *= corr;
        }

        __syncthreads();

#pragma unroll
        for (int j = 0; j < 4; j++)
#pragma unroll
            for (int i = 0; i < 4; i++)
                sKP[(tx * 4 + j) * 64 + ty * 4 + i] = sreg[i][j];
        __syncthreads();

#pragma unroll 8
        for (int t = 0; t < 64; t++) {
            float4 pv = *reinterpret_cast<const float4*>(&sKP[t * 64 + ty * 4]);
            float4 vv = *reinterpret_cast<const float4*>(&sV[t * 64 + tx * 4]);
            float pa[4] = {pv.x, pv.y, pv.z, pv.w};
            float va[4] = {vv.x, vv.y, vv.z, vv.w};
#pragma unroll
            for (int i = 0; i < 4; i++)
#pragma unroll
                for (int j = 0; j < 4; j++)
                    acc[i][j] += pa[i] * va[j];
        }
    }

#pragma unroll
    for (int i = 0; i < 4; i++) {
        const float inv = 1.0f / l[i];
        const int r = s0 + ty * 4 + i;
        float4 o = make_float4(acc[i][0] * inv, acc[i][1] * inv, acc[i][2] * inv, acc[i][3] * inv);
        *reinterpret_cast<float4*>(&g_ctx[(size_t)r * DOUT + h * 64 + tx * 4]) = o;
    }
}

// ---------------- launch ----------------
extern "C" void kernel_launch(void* const* d_in, const int* in_sizes, int n_in,
                              void* d_out, int out_size)
{
    const float* x    = (const float*)d_in[0];
    const float* cosb = (const float*)d_in[2];
    const float* sinb = (const float*)d_in[3];
    const float* Wq   = (const float*)d_in[4];
    const float* Wk   = (const float*)d_in[5];
    const float* Wv   = (const float*)d_in[6];
    const float* Wo   = (const float*)d_in[7];
    const float* qw   = (const float*)d_in[8];
    const float* kw   = (const float*)d_in[9];
    float* out = (float*)d_out;

    (void)in_sizes; (void)n_in; (void)out_size;

    cudaFuncSetAttribute(gemm_q_kernel,  cudaFuncAttributeMaxDynamicSharedMemorySize, GEMM_SMEM);
    cudaFuncSetAttribute(gemm_kv_kernel, cudaFuncAttributeMaxDynamicSharedMemorySize, GEMM_SMEM);
    cudaFuncSetAttribute(gemm_o_kernel,  cudaFuncAttributeMaxDynamicSharedMemorySize, GEMM_SMEM);

    xconv_kernel<<<(SLEN * DIN) / 256, 256>>>(x);
    wconv_q<<<dim3(DOUT / 32, DIN / 32), dim3(32, 8)>>>(Wq);
    wconv_k<<<dim3(KVD / 32, DIN / 32), dim3(32, 8)>>>(Wk);
    wconv_v<<<dim3(KVD / 32, DIN / 32), dim3(32, 8)>>>(Wv);
    wconv_o<<<dim3(DIN / 32, DOUT / 32), dim3(32, 8)>>>(Wo);

    gemm_q_kernel<<<dim3(DOUT / 128, SLEN / 128), 256, GEMM_SMEM>>>();
    gemm_kv_kernel<<<dim3(KVD / 128, SLEN / 128, 2), 256, GEMM_SMEM>>>();

    normrope_kernel<<<dim3(SLEN, 48), 64>>>(cosb, sinb, qw, kw);

    attn_kernel<<<dim3(NH, SLEN / 64), 256>>>();

    ctxconv_kernel<<<(SLEN * DOUT) / 256, 256>>>();
    gemm_o_kernel<<<dim3(DIN / 128, SLEN / 128), 256, GEMM_SMEM>>>(out);
}

// round 4
// speedup vs baseline: 1.7627x; 1.0989x over previous
#include <cuda_runtime.h>
#include <cuda_bf16.h>
#include <math.h>
#include <stdint.h>

// Problem constants
#define SLEN 2048
#define DIN  2048
#define NH   32
#define NKV  8
#define HD   64
#define DOUT 2048   // NH*HD
#define KVD  512    // NKV*HD

// ---------------- scratch (device globals; no allocs allowed) ----------------
__device__ float g_qraw[SLEN * DOUT];   // [s][h*64+d]
__device__ float g_kraw[SLEN * KVD];    // [s][kv*64+d]
__device__ float g_vraw[SLEN * KVD];

// bf16 split operands (A activations row-major [M][K]; weights transposed [N][K])
__device__ __align__(256) __nv_bfloat16 g_xh[SLEN * DIN];
__device__ __align__(256) __nv_bfloat16 g_xl[SLEN * DIN];
__device__ __align__(256) __nv_bfloat16 g_wqh[DOUT * DIN];
__device__ __align__(256) __nv_bfloat16 g_wql[DOUT * DIN];
__device__ __align__(256) __nv_bfloat16 g_wkh[KVD * DIN];
__device__ __align__(256) __nv_bfloat16 g_wkl[KVD * DIN];
__device__ __align__(256) __nv_bfloat16 g_wvh[KVD * DIN];
__device__ __align__(256) __nv_bfloat16 g_wvl[KVD * DIN];
__device__ __align__(256) __nv_bfloat16 g_woh[DIN * DOUT];
__device__ __align__(256) __nv_bfloat16 g_wol[DIN * DOUT];
__device__ __align__(256) __nv_bfloat16 g_ch[SLEN * DOUT];
__device__ __align__(256) __nv_bfloat16 g_cl[SLEN * DOUT];

// attention operands, split bf16
__device__ __align__(256) __nv_bfloat16 g_qh[NH * SLEN * HD];   // [h][s][d]
__device__ __align__(256) __nv_bfloat16 g_ql[NH * SLEN * HD];
__device__ __align__(256) __nv_bfloat16 g_kbh[NKV * SLEN * HD]; // [kv][s][d]
__device__ __align__(256) __nv_bfloat16 g_kbl[NKV * SLEN * HD];
__device__ __align__(256) __nv_bfloat16 g_vth[NKV * HD * SLEN]; // [kv][d][s]
__device__ __align__(256) __nv_bfloat16 g_vtl[NKV * HD * SLEN];

// ---------------- PTX helpers ----------------
__device__ __forceinline__ uint32_t smem_u32(const void* p) {
    uint32_t a;
    asm("{ .reg .u64 t; cvta.to.shared.u64 t, %1; cvt.u32.u64 %0, t; }" : "=r"(a) : "l"(p));
    return a;
}

#define CP_ASYNC16(dst, src) \
    asm volatile("cp.async.cg.shared.global [%0], [%1], 16;" :: "r"(dst), "l"(src) : "memory")
#define CP_COMMIT() asm volatile("cp.async.commit_group;" ::: "memory")
#define CP_WAIT0()  asm volatile("cp.async.wait_group 0;" ::: "memory")
#define CP_WAIT1()  asm volatile("cp.async.wait_group 1;" ::: "memory")

__device__ __forceinline__ void ldsm_x4(uint32_t* r, uint32_t addr) {
    asm volatile("ldmatrix.sync.aligned.m8n8.x4.shared.b16 {%0,%1,%2,%3}, [%4];"
                 : "=r"(r[0]), "=r"(r[1]), "=r"(r[2]), "=r"(r[3]) : "r"(addr));
}
__device__ __forceinline__ void ldsm_x2(uint32_t* r, uint32_t addr) {
    asm volatile("ldmatrix.sync.aligned.m8n8.x2.shared.b16 {%0,%1}, [%2];"
                 : "=r"(r[0]), "=r"(r[1]) : "r"(addr));
}
__device__ __forceinline__ void mma16816(float* c, const uint32_t* a, const uint32_t* b) {
    asm volatile("mma.sync.aligned.m16n8k16.row.col.f32.bf16.bf16.f32 "
                 "{%0,%1,%2,%3}, {%4,%5,%6,%7}, {%8,%9}, {%0,%1,%2,%3};"
                 : "+f"(c[0]), "+f"(c[1]), "+f"(c[2]), "+f"(c[3])
                 : "r"(a[0]), "r"(a[1]), "r"(a[2]), "r"(a[3]), "r"(b[0]), "r"(b[1]));
}

// pack two fp32 -> bf16x2 (lo = first element)
__device__ __forceinline__ uint32_t pack_bf16(float lo, float hi) {
    uint32_t r;
    asm("cvt.rn.bf16x2.f32 %0, %1, %2;" : "=r"(r) : "f"(hi), "f"(lo));
    return r;
}
// split two fp32 into hi bf16x2 and residual-lo bf16x2
__device__ __forceinline__ void split_pair(float a, float b, uint32_t& h, uint32_t& l) {
    h = pack_bf16(a, b);
    __nv_bfloat162 hb = *reinterpret_cast<__nv_bfloat162*>(&h);
    l = pack_bf16(a - __bfloat162float(hb.x), b - __bfloat162float(hb.y));
}

// ---------------- HMMA split-bf16 GEMM: C[M,N] = A[M,K] @ (Bt[N,K])^T ----------------
#define GBK 32
#define LSTR 40
#define TILE_B (128 * LSTR * 2)         // 10240 bytes
#define STAGE_B (4 * TILE_B)
#define GEMM_SMEM (2 * STAGE_B)         // 81920

__device__ __forceinline__ void load_stage(uint32_t stage,
                                           const __nv_bfloat16* __restrict__ Ah,
                                           const __nv_bfloat16* __restrict__ Al,
                                           const __nv_bfloat16* __restrict__ Bh,
                                           const __nv_bfloat16* __restrict__ Bl,
                                           int K, int k0, int tid)
{
    const __nv_bfloat16* tp[4] = {Ah, Al, Bh, Bl};
#pragma unroll
    for (int t = 0; t < 4; t++) {
        const char* src_base = (const char*)tp[t] + (size_t)k0 * 2;
        uint32_t dtile = stage + t * TILE_B;
#pragma unroll
        for (int it = 0; it < 2; it++) {
            int u = tid + it * 256;
            int row = u >> 2;
            int ch = (u & 3) * 16;
            CP_ASYNC16(dtile + row * 80 + ch, src_base + (size_t)row * K * 2 + ch);
        }
    }
    CP_COMMIT();
}

__device__ __forceinline__ void hmma_gemm_body(const __nv_bfloat16* __restrict__ Ah,
                                               const __nv_bfloat16* __restrict__ Al,
                                               const __nv_bfloat16* __restrict__ Bh,
                                               const __nv_bfloat16* __restrict__ Bl,
                                               float* __restrict__ C, int K, int ldc)
{
    extern __shared__ char smem[];
    const uint32_t sb = smem_u32(smem);
    const int tid = threadIdx.x;
    const int wid = tid >> 5;
    const int lane = tid & 31;
    const int gm0 = blockIdx.y * 128;
    const int gn0 = blockIdx.x * 128;
    const int warpM = (wid >> 2) * 64;
    const int warpN = (wid & 3) * 32;
    const int NC = K / GBK;

    const __nv_bfloat16* Ah0 = Ah + (size_t)gm0 * K;
    const __nv_bfloat16* Al0 = Al + (size_t)gm0 * K;
    const __nv_bfloat16* Bh0 = Bh + (size_t)gn0 * K;
    const __nv_bfloat16* Bl0 = Bl + (size_t)gn0 * K;

    float acc[4][4][4];
#pragma unroll
    for (int i = 0; i < 4; i++)
#pragma unroll
        for (int j = 0; j < 4; j++)
#pragma unroll
            for (int v = 0; v < 4; v++) acc[i][j][v] = 0.f;

    const int arow = lane & 15;
    const int acol = (lane >> 4) << 3;
    const int brow = lane & 7;
    const int bcol = ((lane >> 3) & 1) << 3;

    load_stage(sb, Ah0, Al0, Bh0, Bl0, K, 0, tid);

    for (int c = 0; c < NC; c++) {
        if (c + 1 < NC) {
            load_stage(sb + ((c + 1) & 1) * STAGE_B, Ah0, Al0, Bh0, Bl0, K, (c + 1) * GBK, tid);
            CP_WAIT1();
        } else {
            CP_WAIT0();
        }
        __syncthreads();

        const uint32_t base = sb + (c & 1) * STAGE_B;
#pragma unroll
        for (int kk = 0; kk < 32; kk += 16) {
            uint32_t aH[4][4], aL[4][4], bH[4][2], bL[4][2];
#pragma unroll
            for (int mi = 0; mi < 4; mi++) {
                uint32_t ao = (uint32_t)((warpM + mi * 16 + arow) * 80 + (kk + acol) * 2);
                ldsm_x4(aH[mi], base + 0 * TILE_B + ao);
                ldsm_x4(aL[mi], base + 1 * TILE_B + ao);
            }
#pragma unroll
            for (int nj = 0; nj < 4; nj++) {
                uint32_t bo = (uint32_t)((warpN + nj * 8 + brow) * 80 + (kk + bcol) * 2);
                ldsm_x2(bH[nj], base + 2 * TILE_B + bo);
                ldsm_x2(bL[nj], base + 3 * TILE_B + bo);
            }
#pragma unroll
            for (int mi = 0; mi < 4; mi++)
#pragma unroll
                for (int nj = 0; nj < 4; nj++) {
                    mma16816(acc[mi][nj], aH[mi], bH[nj]);
                    mma16816(acc[mi][nj], aL[mi], bH[nj]);
                    mma16816(acc[mi][nj], aH[mi], bL[nj]);
                }
        }
        __syncthreads();
    }

    const int r0 = lane >> 2;
    const int c0 = (lane & 3) * 2;
#pragma unroll
    for (int mi = 0; mi < 4; mi++)
#pragma unroll
        for (int nj = 0; nj < 4; nj++) {
            float* cp = C + (size_t)(gm0 + warpM + mi * 16 + r0) * ldc + gn0 + warpN + nj * 8 + c0;
            *reinterpret_cast<float2*>(cp) = make_float2(acc[mi][nj][0], acc[mi][nj][1]);
            *reinterpret_cast<float2*>(cp + 8 * ldc) = make_float2(acc[mi][nj][2], acc[mi][nj][3]);
        }
}

__global__ __launch_bounds__(256, 1) void gemm_q_kernel() {
    hmma_gemm_body(g_xh, g_xl, g_wqh, g_wql, g_qraw, DIN, DOUT);
}
__global__ __launch_bounds__(256, 1) void gemm_kv_kernel() {
    if (blockIdx.z == 0) hmma_gemm_body(g_xh, g_xl, g_wkh, g_wkl, g_kraw, DIN, KVD);
    else                 hmma_gemm_body(g_xh, g_xl, g_wvh, g_wvl, g_vraw, DIN, KVD);
}
__global__ __launch_bounds__(256, 1) void gemm_o_kernel(float* __restrict__ out) {
    hmma_gemm_body(g_ch, g_cl, g_woh, g_wol, out, DOUT, DIN);
}

// ---------------- converts ----------------
__global__ void xconv_kernel(const float* __restrict__ x) {
    int i = blockIdx.x * 256 + threadIdx.x;
    float v = x[i];
    __nv_bfloat16 h = __float2bfloat16(v);
    g_xh[i] = h;
    g_xl[i] = __float2bfloat16(v - __bfloat162float(h));
}

__device__ __forceinline__ void wconv_body(const float* __restrict__ W,
                                           __nv_bfloat16* __restrict__ Bh,
                                           __nv_bfloat16* __restrict__ Bl,
                                           int R, int Cc)
{
    __shared__ float t[32][33];
    const int c0 = blockIdx.x * 32;
    const int r0 = blockIdx.y * 32;
    const int tx = threadIdx.x;
    const int ty = threadIdx.y;
#pragma unroll
    for (int i = ty; i < 32; i += 8)
        t[i][tx] = W[(size_t)(r0 + i) * Cc + c0 + tx];
    __syncthreads();
#pragma unroll
    for (int i = ty; i < 32; i += 8) {
        float v = t[tx][i];
        size_t o = (size_t)(c0 + i) * R + r0 + tx;
        __nv_bfloat16 h = __float2bfloat16(v);
        Bh[o] = h;
        Bl[o] = __float2bfloat16(v - __bfloat162float(h));
    }
}
__global__ void wconv_q(const float* __restrict__ W) { wconv_body(W, g_wqh, g_wql, DIN, DOUT); }
__global__ void wconv_k(const float* __restrict__ W) { wconv_body(W, g_wkh, g_wkl, DIN, KVD); }
__global__ void wconv_v(const float* __restrict__ W) { wconv_body(W, g_wvh, g_wvl, DIN, KVD); }
__global__ void wconv_o(const float* __restrict__ W) { wconv_body(W, g_woh, g_wol, DOUT, DIN); }

// V: fp32 [s][kv*64+d] -> split bf16 transposed [kv][d][s]
__global__ void vsplit_kernel() {
    __shared__ float t[32][33];
    const int s0 = blockIdx.x * 32;
    const int d0 = blockIdx.y * 32;
    const int kv = blockIdx.z;
    const int tx = threadIdx.x;
    const int ty = threadIdx.y;
#pragma unroll
    for (int i = ty; i < 32; i += 8)
        t[i][tx] = g_vraw[(size_t)(s0 + i) * KVD + kv * 64 + d0 + tx];
    __syncthreads();
#pragma unroll
    for (int i = ty; i < 32; i += 8) {
        float v = t[tx][i];   // vraw[s0+tx][d0+i]
        size_t o = ((size_t)kv * 64 + d0 + i) * SLEN + s0 + tx;
        __nv_bfloat16 h = __float2bfloat16(v);
        g_vth[o] = h;
        g_vtl[o] = __float2bfloat16(v - __bfloat162float(h));
    }
}

// ---------------- RMSNorm + RoPE -> split bf16 ----------------
// grid (S, 40): y<32 q heads, 32..39 k heads. block 64.
__global__ void normrope_kernel(const float* __restrict__ cosb,
                                const float* __restrict__ sinb,
                                const float* __restrict__ qw,
                                const float* __restrict__ kw)
{
    const int s = blockIdx.x;
    const int u = blockIdx.y;
    const int d = threadIdx.x;
    __shared__ float sh[64];
    __shared__ float ssum[2];

    float val;
    const float* w;
    if (u < 32) { val = g_qraw[(size_t)s * DOUT + u * 64 + d]; w = qw; }
    else        { val = g_kraw[(size_t)s * KVD + (u - 32) * 64 + d]; w = kw; }
    float sq = val * val;
#pragma unroll
    for (int mk = 16; mk; mk >>= 1) sq += __shfl_xor_sync(0xffffffffu, sq, mk);
    if ((d & 31) == 0) ssum[d >> 5] = sq;
    __syncthreads();
    float tot = ssum[0] + ssum[1];
    float xn = val * rsqrtf(tot * (1.0f / 64.0f) + 1e-6f) * w[d];
    sh[d] = xn;
    __syncthreads();
    float rot = (d < 32) ? -sh[d + 32] : sh[d - 32];
    float o = xn * cosb[s * 64 + d] + rot * sinb[s * 64 + d];
    __nv_bfloat16 h = __float2bfloat16(o);
    __nv_bfloat16 l = __float2bfloat16(o - __bfloat162float(h));
    if (u < 32) {
        size_t idx = ((size_t)u * SLEN + s) * 64 + d;
        g_qh[idx] = h; g_ql[idx] = l;
    } else {
        size_t idx = ((size_t)(u - 32) * SLEN + s) * 64 + d;
        g_kbh[idx] = h; g_kbl[idx] = l;
    }
}

// ---------------- Flash attention (HMMA split-bf16, causal, GQA) ----------------
// grid (32 heads, 32 q-blocks), 128 threads (4 warps x 16 rows). 64x64 tiles.
#define ATS 144                       // smem row stride bytes (conflict-free, 16B aligned)
#define ATILE (64 * ATS)              // 9216
#define ATT_SMEM (10 * ATILE)         // Qh,Ql + 2 stages x (Kh,Kl,Vh,Vl) = 92160

__global__ __launch_bounds__(128) void attn_kernel()
{
    extern __shared__ char smem[];
    const uint32_t sb = smem_u32(smem);
    const int tid = threadIdx.x;
    const int lane = tid & 31;
    const int wid = tid >> 5;
    const int h = blockIdx.x;
    const int qb = 31 - (int)blockIdx.y;
    const int s0 = qb * 64;
    const int kvh = h >> 2;

    const uint32_t SQH = sb, SQL = sb + ATILE, SKV = sb + 2 * ATILE;

    const char* qh = (const char*)g_qh + (((size_t)h * SLEN + s0) * 64) * 2;
    const char* ql = (const char*)g_ql + (((size_t)h * SLEN + s0) * 64) * 2;
    const char* kh = (const char*)g_kbh + ((size_t)kvh * SLEN * 64) * 2;
    const char* kl = (const char*)g_kbl + ((size_t)kvh * SLEN * 64) * 2;
    const char* vh = (const char*)g_vth + ((size_t)kvh * 64 * SLEN) * 2;
    const char* vl = (const char*)g_vtl + ((size_t)kvh * 64 * SLEN) * 2;

    // Q tiles (hi, lo): 64 rows x 128B
#pragma unroll
    for (int i = 0; i < 4; i++) {
        int u = tid + i * 128;          // 0..511
        int row = u >> 3;
        int ch = (u & 7) * 16;
        CP_ASYNC16(SQH + row * ATS + ch, qh + (size_t)row * 128 + ch);
        CP_ASYNC16(SQL + row * ATS + ch, ql + (size_t)row * 128 + ch);
    }
    // K/V stage 0
    {
        uint32_t base = SKV;
#pragma unroll
        for (int i = 0; i < 4; i++) {
            int u = tid + i * 128;
            int row = u >> 3;
            int ch = (u & 7) * 16;
            CP_ASYNC16(base + 0 * ATILE + row * ATS + ch, kh + (size_t)row * 128 + ch);
            CP_ASYNC16(base + 1 * ATILE + row * ATS + ch, kl + (size_t)row * 128 + ch);
            CP_ASYNC16(base + 2 * ATILE + row * ATS + ch, vh + (size_t)row * SLEN * 2 + ch);
            CP_ASYNC16(base + 3 * ATILE + row * ATS + ch, vl + (size_t)row * SLEN * 2 + ch);
        }
    }
    CP_COMMIT();

    const int warpM = wid * 16;
    const uint32_t a_off = (uint32_t)((warpM + (lane & 15)) * ATS + ((lane >> 4) << 4));
    const uint32_t b_row = (uint32_t)(lane & 7);
    const uint32_t b_colb = (uint32_t)(((lane >> 3) & 1) << 4);

    float m0 = -1e30f, m1 = -1e30f, l0 = 0.f, l1 = 0.f;
    float o[8][4];
#pragma unroll
    for (int j = 0; j < 8; j++)
#pragma unroll
        for (int v = 0; v < 4; v++) o[j][v] = 0.f;

    const float scale = 0.125f;

    for (int kb = 0; kb <= qb; kb++) {
        const int st = kb & 1;
        if (kb < qb) {
            // prefetch next stage
            uint32_t base = SKV + (st ^ 1) * 4 * ATILE;
            const size_t t1 = (size_t)(kb + 1) * 64;
#pragma unroll
            for (int i = 0; i < 4; i++) {
                int u = tid + i * 128;
                int row = u >> 3;
                int ch = (u & 7) * 16;
                CP_ASYNC16(base + 0 * ATILE + row * ATS + ch, kh + (t1 + row) * 128 + ch);
                CP_ASYNC16(base + 1 * ATILE + row * ATS + ch, kl + (t1 + row) * 128 + ch);
                CP_ASYNC16(base + 2 * ATILE + row * ATS + ch, vh + (size_t)row * SLEN * 2 + t1 * 2 + ch);
                CP_ASYNC16(base + 3 * ATILE + row * ATS + ch, vl + (size_t)row * SLEN * 2 + t1 * 2 + ch);
            }
            CP_COMMIT();
            CP_WAIT1();
        } else {
            CP_WAIT0();
        }
        __syncthreads();

        const uint32_t KH = SKV + st * 4 * ATILE;
        const uint32_t KL = KH + ATILE, VH = KL + ATILE, VL = VH + ATILE;

        // ---- scores S = Q K^T ----
        float s_acc[8][4];
#pragma unroll
        for (int j = 0; j < 8; j++)
#pragma unroll
            for (int v = 0; v < 4; v++) s_acc[j][v] = 0.f;

#pragma unroll
        for (int kk = 0; kk < 4; kk++) {
            uint32_t aH[4], aL[4];
            ldsm_x4(aH, SQH + a_off + kk * 32);
            ldsm_x4(aL, SQL + a_off + kk * 32);
#pragma unroll
            for (int nj = 0; nj < 8; nj++) {
                uint32_t bo = (uint32_t)((nj * 8 + b_row) * ATS + kk * 32 + b_colb);
                uint32_t bH[2], bL[2];
                ldsm_x2(bH, KH + bo);
                ldsm_x2(bL, KL + bo);
                mma16816(s_acc[nj], aH, bH);
                mma16816(s_acc[nj], aL, bH);
                mma16816(s_acc[nj], aH, bL);
            }
        }

#pragma unroll
        for (int j = 0; j < 8; j++)
#pragma unroll
            for (int v = 0; v < 4; v++) s_acc[j][v] *= scale;

        if (kb == qb) {
            const int rl0 = warpM + (lane >> 2);
#pragma unroll
            for (int nj = 0; nj < 8; nj++) {
                const int cbase = nj * 8 + (lane & 3) * 2;
#pragma unroll
                for (int e = 0; e < 2; e++) {
                    if (cbase + e > rl0) s_acc[nj][e] = -1e30f;
                    if (cbase + e > rl0 + 8) s_acc[nj][2 + e] = -1e30f;
                }
            }
        }

        // ---- online softmax ----
        float mx0 = -1e30f, mx1 = -1e30f;
#pragma unroll
        for (int nj = 0; nj < 8; nj++) {
            mx0 = fmaxf(mx0, fmaxf(s_acc[nj][0], s_acc[nj][1]));
            mx1 = fmaxf(mx1, fmaxf(s_acc[nj][2], s_acc[nj][3]));
        }
        mx0 = fmaxf(mx0, __shfl_xor_sync(0xffffffffu, mx0, 1));
        mx0 = fmaxf(mx0, __shfl_xor_sync(0xffffffffu, mx0, 2));
        mx1 = fmaxf(mx1, __shfl_xor_sync(0xffffffffu, mx1, 1));
        mx1 = fmaxf(mx1, __shfl_xor_sync(0xffffffffu, mx1, 2));
        const float M0 = fmaxf(m0, mx0), M1 = fmaxf(m1, mx1);
        const float corr0 = __expf(m0 - M0), corr1 = __expf(m1 - M1);
        m0 = M0; m1 = M1;

        float rs0 = 0.f, rs1 = 0.f;
#pragma unroll
        for (int nj = 0; nj < 8; nj++) {
            s_acc[nj][0] = __expf(s_acc[nj][0] - M0);
            s_acc[nj][1] = __expf(s_acc[nj][1] - M0);
            s_acc[nj][2] = __expf(s_acc[nj][2] - M1);
            s_acc[nj][3] = __expf(s_acc[nj][3] - M1);
            rs0 += s_acc[nj][0] + s_acc[nj][1];
            rs1 += s_acc[nj][2] + s_acc[nj][3];
        }
        rs0 += __shfl_xor_sync(0xffffffffu, rs0, 1);
        rs0 += __shfl_xor_sync(0xffffffffu, rs0, 2);
        rs1 += __shfl_xor_sync(0xffffffffu, rs1, 1);
        rs1 += __shfl_xor_sync(0xffffffffu, rs1, 2);
        l0 = l0 * corr0 + rs0;
        l1 = l1 * corr1 + rs1;

#pragma unroll
        for (int j = 0; j < 8; j++) {
            o[j][0] *= corr0; o[j][1] *= corr0;
            o[j][2] *= corr1; o[j][3] *= corr1;
        }

        // ---- PV: o += P V^T ----
#pragma unroll
        for (int kt = 0; kt < 4; kt++) {
            uint32_t pH[4], pL[4];
            split_pair(s_acc[2 * kt][0],     s_acc[2 * kt][1],     pH[0], pL[0]);
            split_pair(s_acc[2 * kt][2],     s_acc[2 * kt][3],     pH[1], pL[1]);
            split_pair(s_acc[2 * kt + 1][0], s_acc[2 * kt + 1][1], pH[2], pL[2]);
            split_pair(s_acc[2 * kt + 1][2], s_acc[2 * kt + 1][3], pH[3], pL[3]);
#pragma unroll
            for (int dj = 0; dj < 8; dj++) {
                uint32_t vo = (uint32_t)((dj * 8 + b_row) * ATS + kt * 32 + b_colb);
                uint32_t vH2[2], vL2[2];
                ldsm_x2(vH2, VH + vo);
                ldsm_x2(vL2, VL + vo);
                mma16816(o[dj], pH, vH2);
                mma16816(o[dj], pL, vH2);
                mma16816(o[dj], pH, vL2);
            }
        }
        __syncthreads();   // all warps done reading this stage before next prefetch
    }

    // ---- epilogue: ctx split bf16 [s][h*64+d] ----
    const float inv0 = 1.0f / l0, inv1 = 1.0f / l1;
    const int r0 = s0 + warpM + (lane >> 2);
    const int r1 = r0 + 8;
    const int cb = h * 64 + (lane & 3) * 2;
#pragma unroll
    for (int dj = 0; dj < 8; dj++) {
        const int col = cb + dj * 8;
        uint32_t hh, ll;
        split_pair(o[dj][0] * inv0, o[dj][1] * inv0, hh, ll);
        *reinterpret_cast<uint32_t*>(&g_ch[(size_t)r0 * DOUT + col]) = hh;
        *reinterpret_cast<uint32_t*>(&g_cl[(size_t)r0 * DOUT + col]) = ll;
        split_pair(o[dj][2] * inv1, o[dj][3] * inv1, hh, ll);
        *reinterpret_cast<uint32_t*>(&g_ch[(size_t)r1 * DOUT + col]) = hh;
        *reinterpret_cast<uint32_t*>(&g_cl[(size_t)r1 * DOUT + col]) = ll;
    }
}

// ---------------- launch ----------------
extern "C" void kernel_launch(void* const* d_in, const int* in_sizes, int n_in,
                              void* d_out, int out_size)
{
    const float* x    = (const float*)d_in[0];
    const float* cosb = (const float*)d_in[2];
    const float* sinb = (const float*)d_in[3];
    const float* Wq   = (const float*)d_in[4];
    const float* Wk   = (const float*)d_in[5];
    const float* Wv   = (const float*)d_in[6];
    const float* Wo   = (const float*)d_in[7];
    const float* qw   = (const float*)d_in[8];
    const float* kw   = (const float*)d_in[9];
    float* out = (float*)d_out;

    (void)in_sizes; (void)n_in; (void)out_size;

    cudaFuncSetAttribute(gemm_q_kernel,  cudaFuncAttributeMaxDynamicSharedMemorySize, GEMM_SMEM);
    cudaFuncSetAttribute(gemm_kv_kernel, cudaFuncAttributeMaxDynamicSharedMemorySize, GEMM_SMEM);
    cudaFuncSetAttribute(gemm_o_kernel,  cudaFuncAttributeMaxDynamicSharedMemorySize, GEMM_SMEM);
    cudaFuncSetAttribute(attn_kernel,    cudaFuncAttributeMaxDynamicSharedMemorySize, ATT_SMEM);

    xconv_kernel<<<(SLEN * DIN) / 256, 256>>>(x);
    wconv_q<<<dim3(DOUT / 32, DIN / 32), dim3(32, 8)>>>(Wq);
    wconv_k<<<dim3(KVD / 32, DIN / 32), dim3(32, 8)>>>(Wk);
    wconv_v<<<dim3(KVD / 32, DIN / 32), dim3(32, 8)>>>(Wv);
    wconv_o<<<dim3(DIN / 32, DOUT / 32), dim3(32, 8)>>>(Wo);

    gemm_q_kernel<<<dim3(DOUT / 128, SLEN / 128), 256, GEMM_SMEM>>>();
    gemm_kv_kernel<<<dim3(KVD / 128, SLEN / 128, 2), 256, GEMM_SMEM>>>();

    normrope_kernel<<<dim3(SLEN, 40), 64>>>(cosb, sinb, qw, kw);
    vsplit_kernel<<<dim3(SLEN / 32, 2, NKV), dim3(32, 8)>>>();

    attn_kernel<<<dim3(NH, 32), 128, ATT_SMEM>>>();

    gemm_o_kernel<<<dim3(DIN / 128, SLEN / 128), 256, GEMM_SMEM>>>(out);
}

// round 5
// speedup vs baseline: 2.6586x; 1.5083x over previous
#include <cuda_runtime.h>
#include <cuda_bf16.h>
#include <math.h>
#include <stdint.h>

// Problem constants
#define SLEN 2048
#define DIN  2048
#define NH   32
#define NKV  8
#define HD   64
#define DOUT 2048   // NH*HD
#define KVD  512    // NKV*HD

// ---------------- scratch (device globals; no allocs allowed) ----------------
__device__ float g_qraw[SLEN * DOUT];   // [s][h*64+d]
__device__ float g_kraw[SLEN * KVD];    // [s][kv*64+d]
__device__ float g_vraw[SLEN * KVD];

// bf16 split operands (A activations row-major [M][K]; weights transposed [N][K])
__device__ __align__(256) __nv_bfloat16 g_xh[SLEN * DIN];
__device__ __align__(256) __nv_bfloat16 g_xl[SLEN * DIN];
__device__ __align__(256) __nv_bfloat16 g_wqh[DOUT * DIN];
__device__ __align__(256) __nv_bfloat16 g_wql[DOUT * DIN];
__device__ __align__(256) __nv_bfloat16 g_wkh[KVD * DIN];
__device__ __align__(256) __nv_bfloat16 g_wkl[KVD * DIN];
__device__ __align__(256) __nv_bfloat16 g_wvh[KVD * DIN];
__device__ __align__(256) __nv_bfloat16 g_wvl[KVD * DIN];
__device__ __align__(256) __nv_bfloat16 g_woh[DIN * DOUT];
__device__ __align__(256) __nv_bfloat16 g_wol[DIN * DOUT];
__device__ __align__(256) __nv_bfloat16 g_ch[SLEN * DOUT];
__device__ __align__(256) __nv_bfloat16 g_cl[SLEN * DOUT];

// attention operands, split bf16
__device__ __align__(256) __nv_bfloat16 g_qh[NH * SLEN * HD];   // [h][s][d]
__device__ __align__(256) __nv_bfloat16 g_ql[NH * SLEN * HD];
__device__ __align__(256) __nv_bfloat16 g_kbh[NKV * SLEN * HD]; // [kv][s][d]
__device__ __align__(256) __nv_bfloat16 g_kbl[NKV * SLEN * HD];
__device__ __align__(256) __nv_bfloat16 g_vth[NKV * HD * SLEN]; // [kv][d][s]
__device__ __align__(256) __nv_bfloat16 g_vtl[NKV * HD * SLEN];

// ---------------- PTX helpers ----------------
__device__ __forceinline__ uint32_t smem_u32(const void* p) {
    uint32_t a;
    asm("{ .reg .u64 t; cvta.to.shared.u64 t, %1; cvt.u32.u64 %0, t; }" : "=r"(a) : "l"(p));
    return a;
}

#define CP_ASYNC16(dst, src) \
    asm volatile("cp.async.cg.shared.global [%0], [%1], 16;" :: "r"(dst), "l"(src) : "memory")
#define CP_COMMIT() asm volatile("cp.async.commit_group;" ::: "memory")
#define CP_WAIT0()  asm volatile("cp.async.wait_group 0;" ::: "memory")
#define CP_WAIT1()  asm volatile("cp.async.wait_group 1;" ::: "memory")

__device__ __forceinline__ void ldsm_x4(uint32_t* r, uint32_t addr) {
    asm volatile("ldmatrix.sync.aligned.m8n8.x4.shared.b16 {%0,%1,%2,%3}, [%4];"
                 : "=r"(r[0]), "=r"(r[1]), "=r"(r[2]), "=r"(r[3]) : "r"(addr));
}
__device__ __forceinline__ void ldsm_x2(uint32_t* r, uint32_t addr) {
    asm volatile("ldmatrix.sync.aligned.m8n8.x2.shared.b16 {%0,%1}, [%2];"
                 : "=r"(r[0]), "=r"(r[1]) : "r"(addr));
}
__device__ __forceinline__ void mma16816(float* c, const uint32_t* a, const uint32_t* b) {
    asm volatile("mma.sync.aligned.m16n8k16.row.col.f32.bf16.bf16.f32 "
                 "{%0,%1,%2,%3}, {%4,%5,%6,%7}, {%8,%9}, {%0,%1,%2,%3};"
                 : "+f"(c[0]), "+f"(c[1]), "+f"(c[2]), "+f"(c[3])
                 : "r"(a[0]), "r"(a[1]), "r"(a[2]), "r"(a[3]), "r"(b[0]), "r"(b[1]));
}

__device__ __forceinline__ uint32_t pack_bf16(float lo, float hi) {
    uint32_t r;
    asm("cvt.rn.bf16x2.f32 %0, %1, %2;" : "=r"(r) : "f"(hi), "f"(lo));
    return r;
}
__device__ __forceinline__ void split_pair(float a, float b, uint32_t& h, uint32_t& l) {
    h = pack_bf16(a, b);
    __nv_bfloat162 hb = *reinterpret_cast<__nv_bfloat162*>(&h);
    l = pack_bf16(a - __bfloat162float(hb.x), b - __bfloat162float(hb.y));
}

// ---------------- HMMA split-bf16 GEMM ----------------
#define GBK 32
#define LSTR 40
#define TILE_B (128 * LSTR * 2)
#define STAGE_B (4 * TILE_B)
#define GEMM_SMEM (2 * STAGE_B)         // 81920

__device__ __forceinline__ void load_stage(uint32_t stage,
                                           const __nv_bfloat16* __restrict__ Ah,
                                           const __nv_bfloat16* __restrict__ Al,
                                           const __nv_bfloat16* __restrict__ Bh,
                                           const __nv_bfloat16* __restrict__ Bl,
                                           int K, int k0, int tid)
{
    const __nv_bfloat16* tp[4] = {Ah, Al, Bh, Bl};
#pragma unroll
    for (int t = 0; t < 4; t++) {
        const char* src_base = (const char*)tp[t] + (size_t)k0 * 2;
        uint32_t dtile = stage + t * TILE_B;
#pragma unroll
        for (int it = 0; it < 2; it++) {
            int u = tid + it * 256;
            int row = u >> 2;
            int ch = (u & 3) * 16;
            CP_ASYNC16(dtile + row * 80 + ch, src_base + (size_t)row * K * 2 + ch);
        }
    }
    CP_COMMIT();
}

__device__ __forceinline__ void hmma_gemm_body(const __nv_bfloat16* __restrict__ Ah,
                                               const __nv_bfloat16* __restrict__ Al,
                                               const __nv_bfloat16* __restrict__ Bh,
                                               const __nv_bfloat16* __restrict__ Bl,
                                               float* __restrict__ C, int K, int ldc)
{
    extern __shared__ char smem[];
    const uint32_t sb = smem_u32(smem);
    const int tid = threadIdx.x;
    const int wid = tid >> 5;
    const int lane = tid & 31;
    const int gm0 = blockIdx.y * 128;
    const int gn0 = blockIdx.x * 128;
    const int warpM = (wid >> 2) * 64;
    const int warpN = (wid & 3) * 32;
    const int NC = K / GBK;

    const __nv_bfloat16* Ah0 = Ah + (size_t)gm0 * K;
    const __nv_bfloat16* Al0 = Al + (size_t)gm0 * K;
    const __nv_bfloat16* Bh0 = Bh + (size_t)gn0 * K;
    const __nv_bfloat16* Bl0 = Bl + (size_t)gn0 * K;

    float acc[4][4][4];
#pragma unroll
    for (int i = 0; i < 4; i++)
#pragma unroll
        for (int j = 0; j < 4; j++)
#pragma unroll
            for (int v = 0; v < 4; v++) acc[i][j][v] = 0.f;

    const int arow = lane & 15;
    const int acol = (lane >> 4) << 3;
    const int brow = lane & 7;
    const int bcol = ((lane >> 3) & 1) << 3;

    load_stage(sb, Ah0, Al0, Bh0, Bl0, K, 0, tid);

    for (int c = 0; c < NC; c++) {
        if (c + 1 < NC) {
            load_stage(sb + ((c + 1) & 1) * STAGE_B, Ah0, Al0, Bh0, Bl0, K, (c + 1) * GBK, tid);
            CP_WAIT1();
        } else {
            CP_WAIT0();
        }
        __syncthreads();

        const uint32_t base = sb + (c & 1) * STAGE_B;
#pragma unroll
        for (int kk = 0; kk < 32; kk += 16) {
            uint32_t aH[4][4], aL[4][4], bH[4][2], bL[4][2];
#pragma unroll
            for (int mi = 0; mi < 4; mi++) {
                uint32_t ao = (uint32_t)((warpM + mi * 16 + arow) * 80 + (kk + acol) * 2);
                ldsm_x4(aH[mi], base + 0 * TILE_B + ao);
                ldsm_x4(aL[mi], base + 1 * TILE_B + ao);
            }
#pragma unroll
            for (int nj = 0; nj < 4; nj++) {
                uint32_t bo = (uint32_t)((warpN + nj * 8 + brow) * 80 + (kk + bcol) * 2);
                ldsm_x2(bH[nj], base + 2 * TILE_B + bo);
                ldsm_x2(bL[nj], base + 3 * TILE_B + bo);
            }
#pragma unroll
            for (int mi = 0; mi < 4; mi++)
#pragma unroll
                for (int nj = 0; nj < 4; nj++) {
                    mma16816(acc[mi][nj], aH[mi], bH[nj]);
                    mma16816(acc[mi][nj], aL[mi], bH[nj]);
                    mma16816(acc[mi][nj], aH[mi], bL[nj]);
                }
        }
        __syncthreads();
    }

    const int r0 = lane >> 2;
    const int c0 = (lane & 3) * 2;
#pragma unroll
    for (int mi = 0; mi < 4; mi++)
#pragma unroll
        for (int nj = 0; nj < 4; nj++) {
            float* cp = C + (size_t)(gm0 + warpM + mi * 16 + r0) * ldc + gn0 + warpN + nj * 8 + c0;
            *reinterpret_cast<float2*>(cp) = make_float2(acc[mi][nj][0], acc[mi][nj][1]);
            *reinterpret_cast<float2*>(cp + 8 * ldc) = make_float2(acc[mi][nj][2], acc[mi][nj][3]);
        }
}

__global__ __launch_bounds__(256, 1) void gemm_q_kernel() {
    hmma_gemm_body(g_xh, g_xl, g_wqh, g_wql, g_qraw, DIN, DOUT);
}
__global__ __launch_bounds__(256, 1) void gemm_kv_kernel() {
    if (blockIdx.z == 0) hmma_gemm_body(g_xh, g_xl, g_wkh, g_wkl, g_kraw, DIN, KVD);
    else                 hmma_gemm_body(g_xh, g_xl, g_wvh, g_wvl, g_vraw, DIN, KVD);
}
__global__ __launch_bounds__(256, 1) void gemm_o_kernel(float* __restrict__ out) {
    hmma_gemm_body(g_ch, g_cl, g_woh, g_wol, out, DOUT, DIN);
}

// ---------------- converts ----------------
__global__ void xconv_kernel(const float* __restrict__ x) {
    int i = blockIdx.x * 256 + threadIdx.x;
    float v = x[i];
    __nv_bfloat16 h = __float2bfloat16(v);
    g_xh[i] = h;
    g_xl[i] = __float2bfloat16(v - __bfloat162float(h));
}

__device__ __forceinline__ void wconv_body(const float* __restrict__ W,
                                           __nv_bfloat16* __restrict__ Bh,
                                           __nv_bfloat16* __restrict__ Bl,
                                           int R, int Cc)
{
    __shared__ float t[32][33];
    const int c0 = blockIdx.x * 32;
    const int r0 = blockIdx.y * 32;
    const int tx = threadIdx.x;
    const int ty = threadIdx.y;
#pragma unroll
    for (int i = ty; i < 32; i += 8)
        t[i][tx] = W[(size_t)(r0 + i) * Cc + c0 + tx];
    __syncthreads();
#pragma unroll
    for (int i = ty; i < 32; i += 8) {
        float v = t[tx][i];
        size_t o = (size_t)(c0 + i) * R + r0 + tx;
        __nv_bfloat16 h = __float2bfloat16(v);
        Bh[o] = h;
        Bl[o] = __float2bfloat16(v - __bfloat162float(h));
    }
}
__global__ void wconv_q(const float* __restrict__ W) { wconv_body(W, g_wqh, g_wql, DIN, DOUT); }
__global__ void wconv_k(const float* __restrict__ W) { wconv_body(W, g_wkh, g_wkl, DIN, KVD); }
__global__ void wconv_v(const float* __restrict__ W) { wconv_body(W, g_wvh, g_wvl, DIN, KVD); }
__global__ void wconv_o(const float* __restrict__ W) { wconv_body(W, g_woh, g_wol, DOUT, DIN); }

// V: fp32 [s][kv*64+d] -> split bf16 transposed [kv][d][s]
__global__ void vsplit_kernel() {
    __shared__ float t[32][33];
    const int s0 = blockIdx.x * 32;
    const int d0 = blockIdx.y * 32;
    const int kv = blockIdx.z;
    const int tx = threadIdx.x;
    const int ty = threadIdx.y;
#pragma unroll
    for (int i = ty; i < 32; i += 8)
        t[i][tx] = g_vraw[(size_t)(s0 + i) * KVD + kv * 64 + d0 + tx];
    __syncthreads();
#pragma unroll
    for (int i = ty; i < 32; i += 8) {
        float v = t[tx][i];
        size_t o = ((size_t)kv * 64 + d0 + i) * SLEN + s0 + tx;
        __nv_bfloat16 h = __float2bfloat16(v);
        g_vth[o] = h;
        g_vtl[o] = __float2bfloat16(v - __bfloat162float(h));
    }
}

// ---------------- RMSNorm + RoPE -> split bf16 ----------------
__global__ void normrope_kernel(const float* __restrict__ cosb,
                                const float* __restrict__ sinb,
                                const float* __restrict__ qw,
                                const float* __restrict__ kw)
{
    const int s = blockIdx.x;
    const int u = blockIdx.y;
    const int d = threadIdx.x;
    __shared__ float sh[64];
    __shared__ float ssum[2];

    float val;
    const float* w;
    if (u < 32) { val = g_qraw[(size_t)s * DOUT + u * 64 + d]; w = qw; }
    else        { val = g_kraw[(size_t)s * KVD + (u - 32) * 64 + d]; w = kw; }
    float sq = val * val;
#pragma unroll
    for (int mk = 16; mk; mk >>= 1) sq += __shfl_xor_sync(0xffffffffu, sq, mk);
    if ((d & 31) == 0) ssum[d >> 5] = sq;
    __syncthreads();
    float tot = ssum[0] + ssum[1];
    float xn = val * rsqrtf(tot * (1.0f / 64.0f) + 1e-6f) * w[d];
    sh[d] = xn;
    __syncthreads();
    float rot = (d < 32) ? -sh[d + 32] : sh[d - 32];
    float o = xn * cosb[s * 64 + d] + rot * sinb[s * 64 + d];
    __nv_bfloat16 h = __float2bfloat16(o);
    __nv_bfloat16 l = __float2bfloat16(o - __bfloat162float(h));
    if (u < 32) {
        size_t idx = ((size_t)u * SLEN + s) * 64 + d;
        g_qh[idx] = h; g_ql[idx] = l;
    } else {
        size_t idx = ((size_t)(u - 32) * SLEN + s) * 64 + d;
        g_kbh[idx] = h; g_kbl[idx] = l;
    }
}

// ---------------- Flash attention (HMMA split-bf16, causal, GQA) ----------------
// grid (32 heads, 16 q-blocks), 256 threads (8 warps x 16 rows). Q tile 128, KV tile 64.
#define ATS 144
#define QTILE (128 * ATS)             // 18432
#define KTILE (64 * ATS)              // 9216
#define ATT_SMEM (2 * QTILE + 8 * KTILE)   // 110592

__global__ __launch_bounds__(256) void attn_kernel()
{
    extern __shared__ char smem[];
    const uint32_t sb = smem_u32(smem);
    const int tid = threadIdx.x;
    const int lane = tid & 31;
    const int wid = tid >> 5;
    const int h = blockIdx.x;
    const int qb = 15 - (int)blockIdx.y;    // heavy blocks first
    const int s0 = qb * 128;
    const int kvh = h >> 2;

    const uint32_t SQH = sb, SQL = sb + QTILE, SKV = sb + 2 * QTILE;

    const char* qh = (const char*)g_qh + (((size_t)h * SLEN + s0) * 64) * 2;
    const char* ql = (const char*)g_ql + (((size_t)h * SLEN + s0) * 64) * 2;
    const char* kh = (const char*)g_kbh + ((size_t)kvh * SLEN * 64) * 2;
    const char* kl = (const char*)g_kbl + ((size_t)kvh * SLEN * 64) * 2;
    const char* vh = (const char*)g_vth + ((size_t)kvh * 64 * SLEN) * 2;
    const char* vl = (const char*)g_vtl + ((size_t)kvh * 64 * SLEN) * 2;

    // Q tiles: 128 rows x 128B each (hi, lo)
#pragma unroll
    for (int i = 0; i < 4; i++) {
        int u = tid + i * 256;          // 0..1023
        int row = u >> 3;
        int ch = (u & 7) * 16;
        CP_ASYNC16(SQH + row * ATS + ch, qh + (size_t)row * 128 + ch);
        CP_ASYNC16(SQL + row * ATS + ch, ql + (size_t)row * 128 + ch);
    }
    // K/V stage 0 (64 rows x 128B per tile)
    {
        uint32_t base = SKV;
#pragma unroll
        for (int i = 0; i < 2; i++) {
            int u = tid + i * 256;      // 0..511
            int row = u >> 3;
            int ch = (u & 7) * 16;
            CP_ASYNC16(base + 0 * KTILE + row * ATS + ch, kh + (size_t)row * 128 + ch);
            CP_ASYNC16(base + 1 * KTILE + row * ATS + ch, kl + (size_t)row * 128 + ch);
            CP_ASYNC16(base + 2 * KTILE + row * ATS + ch, vh + (size_t)row * SLEN * 2 + ch);
            CP_ASYNC16(base + 3 * KTILE + row * ATS + ch, vl + (size_t)row * SLEN * 2 + ch);
        }
    }
    CP_COMMIT();

    const int warpM = wid * 16;
    const uint32_t a_off = (uint32_t)((warpM + (lane & 15)) * ATS + ((lane >> 4) << 4));
    // B-side x4 lane addressing: rows = p*16 + ((lane>>4)&1)*8 + (lane&7), col16 = (lane>>3)&1
    const uint32_t b_rowsel = (uint32_t)((((lane >> 4) & 1) * 8 + (lane & 7)) * ATS +
                                         (((lane >> 3) & 1) << 4));

    float m0 = -1e30f, m1 = -1e30f, l0 = 0.f, l1 = 0.f;
    float o[8][4];
#pragma unroll
    for (int j = 0; j < 8; j++)
#pragma unroll
        for (int v = 0; v < 4; v++) o[j][v] = 0.f;

    const float scale = 0.125f;
    const int kbmax = 2 * qb + 1;

    for (int kb = 0; kb <= kbmax; kb++) {
        const int st = kb & 1;
        const int t0 = kb * 64;
        if (kb < kbmax) {
            uint32_t base = SKV + (st ^ 1) * 4 * KTILE;
            const size_t t1 = (size_t)(kb + 1) * 64;
#pragma unroll
            for (int i = 0; i < 2; i++) {
                int u = tid + i * 256;
                int row = u >> 3;
                int ch = (u & 7) * 16;
                CP_ASYNC16(base + 0 * KTILE + row * ATS + ch, kh + (t1 + row) * 128 + ch);
                CP_ASYNC16(base + 1 * KTILE + row * ATS + ch, kl + (t1 + row) * 128 + ch);
                CP_ASYNC16(base + 2 * KTILE + row * ATS + ch, vh + (size_t)row * SLEN * 2 + t1 * 2 + ch);
                CP_ASYNC16(base + 3 * KTILE + row * ATS + ch, vl + (size_t)row * SLEN * 2 + t1 * 2 + ch);
            }
            CP_COMMIT();
            CP_WAIT1();
        } else {
            CP_WAIT0();
        }
        __syncthreads();

        const uint32_t KH = SKV + st * 4 * KTILE;
        const uint32_t KL = KH + KTILE, VH = KL + KTILE, VL = VH + KTILE;

        // ---- scores S = Q K^T (16 rows x 64 cols per warp) ----
        float s_acc[8][4];
#pragma unroll
        for (int j = 0; j < 8; j++)
#pragma unroll
            for (int v = 0; v < 4; v++) s_acc[j][v] = 0.f;

#pragma unroll
        for (int kk = 0; kk < 4; kk++) {
            uint32_t aH[4], aL[4];
            ldsm_x4(aH, SQH + a_off + kk * 32);
            ldsm_x4(aL, SQL + a_off + kk * 32);
#pragma unroll
            for (int p = 0; p < 4; p++) {
                uint32_t bo = (uint32_t)(p * 16 * ATS) + b_rowsel + kk * 32;
                uint32_t bH4[4], bL4[4];
                ldsm_x4(bH4, KH + bo);
                ldsm_x4(bL4, KL + bo);
                mma16816(s_acc[2 * p],     aH, bH4);
                mma16816(s_acc[2 * p],     aL, bH4);
                mma16816(s_acc[2 * p],     aH, bL4);
                mma16816(s_acc[2 * p + 1], aH, bH4 + 2);
                mma16816(s_acc[2 * p + 1], aL, bH4 + 2);
                mma16816(s_acc[2 * p + 1], aH, bL4 + 2);
            }
        }

#pragma unroll
        for (int j = 0; j < 8; j++)
#pragma unroll
            for (int v = 0; v < 4; v++) s_acc[j][v] *= scale;

        // causal mask (only blocks overlapping the diagonal)
        if (t0 + 63 > s0 + warpM) {
            const int rg0 = s0 + warpM + (lane >> 2);
#pragma unroll
            for (int nj = 0; nj < 8; nj++) {
                const int cg = t0 + nj * 8 + (lane & 3) * 2;
#pragma unroll
                for (int e = 0; e < 2; e++) {
                    if (cg + e > rg0) s_acc[nj][e] = -1e30f;
                    if (cg + e > rg0 + 8) s_acc[nj][2 + e] = -1e30f;
                }
            }
        }

        // ---- online softmax ----
        float mx0 = -1e30f, mx1 = -1e30f;
#pragma unroll
        for (int nj = 0; nj < 8; nj++) {
            mx0 = fmaxf(mx0, fmaxf(s_acc[nj][0], s_acc[nj][1]));
            mx1 = fmaxf(mx1, fmaxf(s_acc[nj][2], s_acc[nj][3]));
        }
        mx0 = fmaxf(mx0, __shfl_xor_sync(0xffffffffu, mx0, 1));
        mx0 = fmaxf(mx0, __shfl_xor_sync(0xffffffffu, mx0, 2));
        mx1 = fmaxf(mx1, __shfl_xor_sync(0xffffffffu, mx1, 1));
        mx1 = fmaxf(mx1, __shfl_xor_sync(0xffffffffu, mx1, 2));
        const float M0 = fmaxf(m0, mx0), M1 = fmaxf(m1, mx1);
        const float corr0 = __expf(m0 - M0), corr1 = __expf(m1 - M1);
        m0 = M0; m1 = M1;

        float rs0 = 0.f, rs1 = 0.f;
#pragma unroll
        for (int nj = 0; nj < 8; nj++) {
            s_acc[nj][0] = __expf(s_acc[nj][0] - M0);
            s_acc[nj][1] = __expf(s_acc[nj][1] - M0);
            s_acc[nj][2] = __expf(s_acc[nj][2] - M1);
            s_acc[nj][3] = __expf(s_acc[nj][3] - M1);
            rs0 += s_acc[nj][0] + s_acc[nj][1];
            rs1 += s_acc[nj][2] + s_acc[nj][3];
        }
        rs0 += __shfl_xor_sync(0xffffffffu, rs0, 1);
        rs0 += __shfl_xor_sync(0xffffffffu, rs0, 2);
        rs1 += __shfl_xor_sync(0xffffffffu, rs1, 1);
        rs1 += __shfl_xor_sync(0xffffffffu, rs1, 2);
        l0 = l0 * corr0 + rs0;
        l1 = l1 * corr1 + rs1;

#pragma unroll
        for (int j = 0; j < 8; j++) {
            o[j][0] *= corr0; o[j][1] *= corr0;
            o[j][2] *= corr1; o[j][3] *= corr1;
        }

        // ---- PV: o += P V^T ----
#pragma unroll
        for (int kt = 0; kt < 4; kt++) {
            uint32_t pH[4], pL[4];
            split_pair(s_acc[2 * kt][0],     s_acc[2 * kt][1],     pH[0], pL[0]);
            split_pair(s_acc[2 * kt][2],     s_acc[2 * kt][3],     pH[1], pL[1]);
            split_pair(s_acc[2 * kt + 1][0], s_acc[2 * kt + 1][1], pH[2], pL[2]);
            split_pair(s_acc[2 * kt + 1][2], s_acc[2 * kt + 1][3], pH[3], pL[3]);
#pragma unroll
            for (int p = 0; p < 4; p++) {
                uint32_t vo = (uint32_t)(p * 16 * ATS) + b_rowsel + kt * 32;
                uint32_t vH4[4], vL4[4];
                ldsm_x4(vH4, VH + vo);
                ldsm_x4(vL4, VL + vo);
                mma16816(o[2 * p],     pH, vH4);
                mma16816(o[2 * p],     pL, vH4);
                mma16816(o[2 * p],     pH, vL4);
                mma16816(o[2 * p + 1], pH, vH4 + 2);
                mma16816(o[2 * p + 1], pL, vH4 + 2);
                mma16816(o[2 * p + 1], pH, vL4 + 2);
            }
        }
        __syncthreads();
    }

    // ---- epilogue: ctx split bf16 [s][h*64+d] ----
    const float inv0 = 1.0f / l0, inv1 = 1.0f / l1;
    const int r0 = s0 + warpM + (lane >> 2);
    const int r1 = r0 + 8;
    const int cb = h * 64 + (lane & 3) * 2;
#pragma unroll
    for (int dj = 0; dj < 8; dj++) {
        const int col = cb + dj * 8;
        uint32_t hh, ll;
        split_pair(o[dj][0] * inv0, o[dj][1] * inv0, hh, ll);
        *reinterpret_cast<uint32_t*>(&g_ch[(size_t)r0 * DOUT + col]) = hh;
        *reinterpret_cast<uint32_t*>(&g_cl[(size_t)r0 * DOUT + col]) = ll;
        split_pair(o[dj][2] * inv1, o[dj][3] * inv1, hh, ll);
        *reinterpret_cast<uint32_t*>(&g_ch[(size_t)r1 * DOUT + col]) = hh;
        *reinterpret_cast<uint32_t*>(&g_cl[(size_t)r1 * DOUT + col]) = ll;
    }
}

// ---------------- launch ----------------
extern "C" void kernel_launch(void* const* d_in, const int* in_sizes, int n_in,
                              void* d_out, int out_size)
{
    const float* x    = (const float*)d_in[0];
    const float* cosb = (const float*)d_in[2];
    const float* sinb = (const float*)d_in[3];
    const float* Wq   = (const float*)d_in[4];
    const float* Wk   = (const float*)d_in[5];
    const float* Wv   = (const float*)d_in[6];
    const float* Wo   = (const float*)d_in[7];
    const float* qw   = (const float*)d_in[8];
    const float* kw   = (const float*)d_in[9];
    float* out = (float*)d_out;

    (void)in_sizes; (void)n_in; (void)out_size;

    cudaFuncSetAttribute(gemm_q_kernel,  cudaFuncAttributeMaxDynamicSharedMemorySize, GEMM_SMEM);
    cudaFuncSetAttribute(gemm_kv_kernel, cudaFuncAttributeMaxDynamicSharedMemorySize, GEMM_SMEM);
    cudaFuncSetAttribute(gemm_o_kernel,  cudaFuncAttributeMaxDynamicSharedMemorySize, GEMM_SMEM);
    cudaFuncSetAttribute(attn_kernel,    cudaFuncAttributeMaxDynamicSharedMemorySize, ATT_SMEM);

    xconv_kernel<<<(SLEN * DIN) / 256, 256>>>(x);
    wconv_q<<<dim3(DOUT / 32, DIN / 32), dim3(32, 8)>>>(Wq);
    wconv_k<<<dim3(KVD / 32, DIN / 32), dim3(32, 8)>>>(Wk);
    wconv_v<<<dim3(KVD / 32, DIN / 32), dim3(32, 8)>>>(Wv);
    wconv_o<<<dim3(DIN / 32, DOUT / 32), dim3(32, 8)>>>(Wo);

    gemm_q_kernel<<<dim3(DOUT / 128, SLEN / 128), 256, GEMM_SMEM>>>();
    gemm_kv_kernel<<<dim3(KVD / 128, SLEN / 128, 2), 256, GEMM_SMEM>>>();

    normrope_kernel<<<dim3(SLEN, 40), 64>>>(cosb, sinb, qw, kw);
    vsplit_kernel<<<dim3(SLEN / 32, 2, NKV), dim3(32, 8)>>>();

    attn_kernel<<<dim3(NH, 16), 256, ATT_SMEM>>>();

    gemm_o_kernel<<<dim3(DIN / 128, SLEN / 128), 256, GEMM_SMEM>>>(out);
}

// round 6
// speedup vs baseline: 2.9398x; 1.1058x over previous
#include <cuda_runtime.h>
#include <cuda_bf16.h>
#include <math.h>
#include <stdint.h>

// Problem constants
#define SLEN 2048
#define DIN  2048
#define NH   32
#define NKV  8
#define HD   64
#define DOUT 2048   // NH*HD
#define KVD  512    // NKV*HD

// ---------------- scratch (device globals; no allocs allowed) ----------------
__device__ float g_qraw[SLEN * DOUT];   // [s][h*64+d]
__device__ float g_kraw[SLEN * KVD];    // [s][kv*64+d]
__device__ float g_vraw[SLEN * KVD];

// bf16 split operands (A activations row-major [M][K]; weights transposed [N][K])
__device__ __align__(256) __nv_bfloat16 g_xh[SLEN * DIN];
__device__ __align__(256) __nv_bfloat16 g_xl[SLEN * DIN];
__device__ __align__(256) __nv_bfloat16 g_wqh[DOUT * DIN];
__device__ __align__(256) __nv_bfloat16 g_wql[DOUT * DIN];
__device__ __align__(256) __nv_bfloat16 g_wkh[KVD * DIN];
__device__ __align__(256) __nv_bfloat16 g_wkl[KVD * DIN];
__device__ __align__(256) __nv_bfloat16 g_wvh[KVD * DIN];
__device__ __align__(256) __nv_bfloat16 g_wvl[KVD * DIN];
__device__ __align__(256) __nv_bfloat16 g_woh[DIN * DOUT];
__device__ __align__(256) __nv_bfloat16 g_wol[DIN * DOUT];
__device__ __align__(256) __nv_bfloat16 g_ch[SLEN * DOUT];
__device__ __align__(256) __nv_bfloat16 g_cl[SLEN * DOUT];

// attention operands, split bf16
__device__ __align__(256) __nv_bfloat16 g_qh[NH * SLEN * HD];   // [h][s][d]
__device__ __align__(256) __nv_bfloat16 g_ql[NH * SLEN * HD];
__device__ __align__(256) __nv_bfloat16 g_kbh[NKV * SLEN * HD]; // [kv][s][d]
__device__ __align__(256) __nv_bfloat16 g_kbl[NKV * SLEN * HD];
__device__ __align__(256) __nv_bfloat16 g_vth[NKV * HD * SLEN]; // [kv][d][s]
__device__ __align__(256) __nv_bfloat16 g_vtl[NKV * HD * SLEN];

// ---------------- PTX helpers ----------------
__device__ __forceinline__ uint32_t smem_u32(const void* p) {
    uint32_t a;
    asm("{ .reg .u64 t; cvta.to.shared.u64 t, %1; cvt.u32.u64 %0, t; }" : "=r"(a) : "l"(p));
    return a;
}

#define CP_ASYNC16(dst, src) \
    asm volatile("cp.async.cg.shared.global [%0], [%1], 16;" :: "r"(dst), "l"(src) : "memory")
#define CP_COMMIT() asm volatile("cp.async.commit_group;" ::: "memory")
#define CP_WAIT0()  asm volatile("cp.async.wait_group 0;" ::: "memory")
#define CP_WAIT1()  asm volatile("cp.async.wait_group 1;" ::: "memory")

__device__ __forceinline__ void ldsm_x4(uint32_t* r, uint32_t addr) {
    asm volatile("ldmatrix.sync.aligned.m8n8.x4.shared.b16 {%0,%1,%2,%3}, [%4];"
                 : "=r"(r[0]), "=r"(r[1]), "=r"(r[2]), "=r"(r[3]) : "r"(addr));
}
__device__ __forceinline__ void mma16816(float* c, const uint32_t* a, const uint32_t* b) {
    asm volatile("mma.sync.aligned.m16n8k16.row.col.f32.bf16.bf16.f32 "
                 "{%0,%1,%2,%3}, {%4,%5,%6,%7}, {%8,%9}, {%0,%1,%2,%3};"
                 : "+f"(c[0]), "+f"(c[1]), "+f"(c[2]), "+f"(c[3])
                 : "r"(a[0]), "r"(a[1]), "r"(a[2]), "r"(a[3]), "r"(b[0]), "r"(b[1]));
}

__device__ __forceinline__ uint32_t pack_bf16(float lo, float hi) {
    uint32_t r;
    asm("cvt.rn.bf16x2.f32 %0, %1, %2;" : "=r"(r) : "f"(hi), "f"(lo));
    return r;
}
__device__ __forceinline__ void split_pair(float a, float b, uint32_t& h, uint32_t& l) {
    h = pack_bf16(a, b);
    __nv_bfloat162 hb = *reinterpret_cast<__nv_bfloat162*>(&h);
    l = pack_bf16(a - __bfloat162float(hb.x), b - __bfloat162float(hb.y));
}

// ---------------- HMMA split-bf16 GEMM: C[M,N] = A[M,K] @ (Bt[N,K])^T ----------------
// CTA 128x128, BK=64, 256 threads (8 warps as 2x4), 3-stage cp.async pipeline.
#define GBK 64
#define GROW 144                         // smem row stride bytes (64 bf16 + 8 pad)
#define TILE_B (128 * GROW)              // 18432
#define STAGE_B (4 * TILE_B)             // 73728 (Ah, Al, Bh, Bl)
#define GEMM_SMEM (3 * STAGE_B)          // 221184

__device__ __forceinline__ void load_stage(uint32_t stage,
                                           const __nv_bfloat16* __restrict__ Ah,
                                           const __nv_bfloat16* __restrict__ Al,
                                           const __nv_bfloat16* __restrict__ Bh,
                                           const __nv_bfloat16* __restrict__ Bl,
                                           int K, int k0, int tid)
{
    const __nv_bfloat16* tp[4] = {Ah, Al, Bh, Bl};
#pragma unroll
    for (int t = 0; t < 4; t++) {
        const char* src_base = (const char*)tp[t] + (size_t)k0 * 2;
        uint32_t dtile = stage + t * TILE_B;
#pragma unroll
        for (int it = 0; it < 4; it++) {
            int u = tid + it * 256;       // 0..1023
            int row = u >> 3;             // 0..127
            int ch = (u & 7) * 16;        // 0..112
            CP_ASYNC16(dtile + row * GROW + ch, src_base + (size_t)row * K * 2 + ch);
        }
    }
    CP_COMMIT();
}

__device__ __forceinline__ void hmma_gemm_body(const __nv_bfloat16* __restrict__ Ah,
                                               const __nv_bfloat16* __restrict__ Al,
                                               const __nv_bfloat16* __restrict__ Bh,
                                               const __nv_bfloat16* __restrict__ Bl,
                                               float* __restrict__ C, int K, int ldc)
{
    extern __shared__ char smem[];
    const uint32_t sb = smem_u32(smem);
    const int tid = threadIdx.x;
    const int wid = tid >> 5;
    const int lane = tid & 31;
    const int gm0 = blockIdx.y * 128;
    const int gn0 = blockIdx.x * 128;
    const int warpM = (wid >> 2) * 64;
    const int warpN = (wid & 3) * 32;
    const int NC = K / GBK;

    const __nv_bfloat16* Ah0 = Ah + (size_t)gm0 * K;
    const __nv_bfloat16* Al0 = Al + (size_t)gm0 * K;
    const __nv_bfloat16* Bh0 = Bh + (size_t)gn0 * K;
    const __nv_bfloat16* Bl0 = Bl + (size_t)gn0 * K;

    float acc[4][4][4];
#pragma unroll
    for (int i = 0; i < 4; i++)
#pragma unroll
        for (int j = 0; j < 4; j++)
#pragma unroll
            for (int v = 0; v < 4; v++) acc[i][j][v] = 0.f;

    // A-side ldsm_x4 (16x16): rows warpM+mi*16+(lane&15), 16B col = (lane>>4)
    const uint32_t a_off = (uint32_t)((warpM + (lane & 15)) * GROW + ((lane >> 4) << 4));
    // B-side ldsm_x4 (two n8 tiles): rows = p*16 + ((lane>>4)&1)*8 + (lane&7)
    const uint32_t b_rowsel = (uint32_t)((warpN + ((lane >> 4) & 1) * 8 + (lane & 7)) * GROW +
                                         (((lane >> 3) & 1) << 4));

    load_stage(sb + 0 * STAGE_B, Ah0, Al0, Bh0, Bl0, K, 0, tid);
    load_stage(sb + 1 * STAGE_B, Ah0, Al0, Bh0, Bl0, K, GBK, tid);

    for (int c = 0; c < NC; c++) {
        if (c + 1 < NC) { CP_WAIT1(); } else { CP_WAIT0(); }
        __syncthreads();

        if (c + 2 < NC)
            load_stage(sb + ((c + 2) % 3) * STAGE_B, Ah0, Al0, Bh0, Bl0, K, (c + 2) * GBK, tid);

        const uint32_t base = sb + (c % 3) * STAGE_B;
#pragma unroll
        for (int kk = 0; kk < 64; kk += 16) {
            uint32_t aH[4][4], aL[4][4], bH4[2][4], bL4[2][4];
#pragma unroll
            for (int mi = 0; mi < 4; mi++) {
                uint32_t ao = a_off + (uint32_t)(mi * 16 * GROW) + kk * 2;
                ldsm_x4(aH[mi], base + 0 * TILE_B + ao);
                ldsm_x4(aL[mi], base + 1 * TILE_B + ao);
            }
#pragma unroll
            for (int p = 0; p < 2; p++) {
                uint32_t bo = b_rowsel + (uint32_t)(p * 16 * GROW) + kk * 2;
                ldsm_x4(bH4[p], base + 2 * TILE_B + bo);
                ldsm_x4(bL4[p], base + 3 * TILE_B + bo);
            }
#pragma unroll
            for (int mi = 0; mi < 4; mi++)
#pragma unroll
                for (int p = 0; p < 2; p++) {
                    mma16816(acc[mi][2 * p],     aH[mi], bH4[p]);
                    mma16816(acc[mi][2 * p],     aL[mi], bH4[p]);
                    mma16816(acc[mi][2 * p],     aH[mi], bL4[p]);
                    mma16816(acc[mi][2 * p + 1], aH[mi], bH4[p] + 2);
                    mma16816(acc[mi][2 * p + 1], aL[mi], bH4[p] + 2);
                    mma16816(acc[mi][2 * p + 1], aH[mi], bL4[p] + 2);
                }
        }
    }

    const int r0 = lane >> 2;
    const int c0 = (lane & 3) * 2;
#pragma unroll
    for (int mi = 0; mi < 4; mi++)
#pragma unroll
        for (int nj = 0; nj < 4; nj++) {
            float* cp = C + (size_t)(gm0 + warpM + mi * 16 + r0) * ldc + gn0 + warpN + nj * 8 + c0;
            *reinterpret_cast<float2*>(cp) = make_float2(acc[mi][nj][0], acc[mi][nj][1]);
            *reinterpret_cast<float2*>(cp + 8 * ldc) = make_float2(acc[mi][nj][2], acc[mi][nj][3]);
        }
}

__global__ __launch_bounds__(256, 1) void gemm_q_kernel() {
    hmma_gemm_body(g_xh, g_xl, g_wqh, g_wql, g_qraw, DIN, DOUT);
}
__global__ __launch_bounds__(256, 1) void gemm_kv_kernel() {
    if (blockIdx.z == 0) hmma_gemm_body(g_xh, g_xl, g_wkh, g_wkl, g_kraw, DIN, KVD);
    else                 hmma_gemm_body(g_xh, g_xl, g_wvh, g_wvl, g_vraw, DIN, KVD);
}
__global__ __launch_bounds__(256, 1) void gemm_o_kernel(float* __restrict__ out) {
    hmma_gemm_body(g_ch, g_cl, g_woh, g_wol, out, DOUT, DIN);
}

// ---------------- converts ----------------
__global__ void xconv_kernel(const float* __restrict__ x) {
    int i = blockIdx.x * 256 + threadIdx.x;
    float v = x[i];
    __nv_bfloat16 h = __float2bfloat16(v);
    g_xh[i] = h;
    g_xl[i] = __float2bfloat16(v - __bfloat162float(h));
}

__device__ __forceinline__ void wconv_body(const float* __restrict__ W,
                                           __nv_bfloat16* __restrict__ Bh,
                                           __nv_bfloat16* __restrict__ Bl,
                                           int R, int Cc)
{
    __shared__ float t[32][33];
    const int c0 = blockIdx.x * 32;
    const int r0 = blockIdx.y * 32;
    const int tx = threadIdx.x;
    const int ty = threadIdx.y;
#pragma unroll
    for (int i = ty; i < 32; i += 8)
        t[i][tx] = W[(size_t)(r0 + i) * Cc + c0 + tx];
    __syncthreads();
#pragma unroll
    for (int i = ty; i < 32; i += 8) {
        float v = t[tx][i];
        size_t o = (size_t)(c0 + i) * R + r0 + tx;
        __nv_bfloat16 h = __float2bfloat16(v);
        Bh[o] = h;
        Bl[o] = __float2bfloat16(v - __bfloat162float(h));
    }
}
__global__ void wconv_q(const float* __restrict__ W) { wconv_body(W, g_wqh, g_wql, DIN, DOUT); }
__global__ void wconv_k(const float* __restrict__ W) { wconv_body(W, g_wkh, g_wkl, DIN, KVD); }
__global__ void wconv_v(const float* __restrict__ W) { wconv_body(W, g_wvh, g_wvl, DIN, KVD); }
__global__ void wconv_o(const float* __restrict__ W) { wconv_body(W, g_woh, g_wol, DOUT, DIN); }

// V: fp32 [s][kv*64+d] -> split bf16 transposed [kv][d][s]
__global__ void vsplit_kernel() {
    __shared__ float t[32][33];
    const int s0 = blockIdx.x * 32;
    const int d0 = blockIdx.y * 32;
    const int kv = blockIdx.z;
    const int tx = threadIdx.x;
    const int ty = threadIdx.y;
#pragma unroll
    for (int i = ty; i < 32; i += 8)
        t[i][tx] = g_vraw[(size_t)(s0 + i) * KVD + kv * 64 + d0 + tx];
    __syncthreads();
#pragma unroll
    for (int i = ty; i < 32; i += 8) {
        float v = t[tx][i];
        size_t o = ((size_t)kv * 64 + d0 + i) * SLEN + s0 + tx;
        __nv_bfloat16 h = __float2bfloat16(v);
        g_vth[o] = h;
        g_vtl[o] = __float2bfloat16(v - __bfloat162float(h));
    }
}

// ---------------- RMSNorm + RoPE -> split bf16 ----------------
__global__ void normrope_kernel(const float* __restrict__ cosb,
                                const float* __restrict__ sinb,
                                const float* __restrict__ qw,
                                const float* __restrict__ kw)
{
    const int s = blockIdx.x;
    const int u = blockIdx.y;
    const int d = threadIdx.x;
    __shared__ float sh[64];
    __shared__ float ssum[2];

    float val;
    const float* w;
    if (u < 32) { val = g_qraw[(size_t)s * DOUT + u * 64 + d]; w = qw; }
    else        { val = g_kraw[(size_t)s * KVD + (u - 32) * 64 + d]; w = kw; }
    float sq = val * val;
#pragma unroll
    for (int mk = 16; mk; mk >>= 1) sq += __shfl_xor_sync(0xffffffffu, sq, mk);
    if ((d & 31) == 0) ssum[d >> 5] = sq;
    __syncthreads();
    float tot = ssum[0] + ssum[1];
    float xn = val * rsqrtf(tot * (1.0f / 64.0f) + 1e-6f) * w[d];
    sh[d] = xn;
    __syncthreads();
    float rot = (d < 32) ? -sh[d + 32] : sh[d - 32];
    float o = xn * cosb[s * 64 + d] + rot * sinb[s * 64 + d];
    __nv_bfloat16 h = __float2bfloat16(o);
    __nv_bfloat16 l = __float2bfloat16(o - __bfloat162float(h));
    if (u < 32) {
        size_t idx = ((size_t)u * SLEN + s) * 64 + d;
        g_qh[idx] = h; g_ql[idx] = l;
    } else {
        size_t idx = ((size_t)(u - 32) * SLEN + s) * 64 + d;
        g_kbh[idx] = h; g_kbl[idx] = l;
    }
}

// ---------------- Flash attention (HMMA split-bf16, causal, GQA) ----------------
// grid (32 heads, 16 q-blocks), 256 threads (8 warps x 16 rows). Q tile 128, KV tile 64.
#define ATS 144
#define QTILE (128 * ATS)             // 18432
#define KTILE (64 * ATS)              // 9216
#define ATT_SMEM (2 * QTILE + 8 * KTILE)   // 110592

__global__ __launch_bounds__(256) void attn_kernel()
{
    extern __shared__ char smem[];
    const uint32_t sb = smem_u32(smem);
    const int tid = threadIdx.x;
    const int lane = tid & 31;
    const int wid = tid >> 5;
    const int h = blockIdx.x;
    const int qb = 15 - (int)blockIdx.y;    // heavy blocks first
    const int s0 = qb * 128;
    const int kvh = h >> 2;

    const uint32_t SQH = sb, SQL = sb + QTILE, SKV = sb + 2 * QTILE;

    const char* qh = (const char*)g_qh + (((size_t)h * SLEN + s0) * 64) * 2;
    const char* ql = (const char*)g_ql + (((size_t)h * SLEN + s0) * 64) * 2;
    const char* kh = (const char*)g_kbh + ((size_t)kvh * SLEN * 64) * 2;
    const char* kl = (const char*)g_kbl + ((size_t)kvh * SLEN * 64) * 2;
    const char* vh = (const char*)g_vth + ((size_t)kvh * 64 * SLEN) * 2;
    const char* vl = (const char*)g_vtl + ((size_t)kvh * 64 * SLEN) * 2;

#pragma unroll
    for (int i = 0; i < 4; i++) {
        int u = tid + i * 256;
        int row = u >> 3;
        int ch = (u & 7) * 16;
        CP_ASYNC16(SQH + row * ATS + ch, qh + (size_t)row * 128 + ch);
        CP_ASYNC16(SQL + row * ATS + ch, ql + (size_t)row * 128 + ch);
    }
    {
        uint32_t base = SKV;
#pragma unroll
        for (int i = 0; i < 2; i++) {
            int u = tid + i * 256;
            int row = u >> 3;
            int ch = (u & 7) * 16;
            CP_ASYNC16(base + 0 * KTILE + row * ATS + ch, kh + (size_t)row * 128 + ch);
            CP_ASYNC16(base + 1 * KTILE + row * ATS + ch, kl + (size_t)row * 128 + ch);
            CP_ASYNC16(base + 2 * KTILE + row * ATS + ch, vh + (size_t)row * SLEN * 2 + ch);
            CP_ASYNC16(base + 3 * KTILE + row * ATS + ch, vl + (size_t)row * SLEN * 2 + ch);
        }
    }
    CP_COMMIT();

    const int warpM = wid * 16;
    const uint32_t a_off = (uint32_t)((warpM + (lane & 15)) * ATS + ((lane >> 4) << 4));
    const uint32_t b_rowsel = (uint32_t)((((lane >> 4) & 1) * 8 + (lane & 7)) * ATS +
                                         (((lane >> 3) & 1) << 4));

    float m0 = -1e30f, m1 = -1e30f, l0 = 0.f, l1 = 0.f;
    float o[8][4];
#pragma unroll
    for (int j = 0; j < 8; j++)
#pragma unroll
        for (int v = 0; v < 4; v++) o[j][v] = 0.f;

    const float scale = 0.125f;
    const int kbmax = 2 * qb + 1;

    for (int kb = 0; kb <= kbmax; kb++) {
        const int st = kb & 1;
        const int t0 = kb * 64;
        if (kb < kbmax) {
            uint32_t base = SKV + (st ^ 1) * 4 * KTILE;
            const size_t t1 = (size_t)(kb + 1) * 64;
#pragma unroll
            for (int i = 0; i < 2; i++) {
                int u = tid + i * 256;
                int row = u >> 3;
                int ch = (u & 7) * 16;
                CP_ASYNC16(base + 0 * KTILE + row * ATS + ch, kh + (t1 + row) * 128 + ch);
                CP_ASYNC16(base + 1 * KTILE + row * ATS + ch, kl + (t1 + row) * 128 + ch);
                CP_ASYNC16(base + 2 * KTILE + row * ATS + ch, vh + (size_t)row * SLEN * 2 + t1 * 2 + ch);
                CP_ASYNC16(base + 3 * KTILE + row * ATS + ch, vl + (size_t)row * SLEN * 2 + t1 * 2 + ch);
            }
            CP_COMMIT();
            CP_WAIT1();
        } else {
            CP_WAIT0();
        }
        __syncthreads();

        const uint32_t KH = SKV + st * 4 * KTILE;
        const uint32_t KL = KH + KTILE, VH = KL + KTILE, VL = VH + KTILE;

        float s_acc[8][4];
#pragma unroll
        for (int j = 0; j < 8; j++)
#pragma unroll
            for (int v = 0; v < 4; v++) s_acc[j][v] = 0.f;

#pragma unroll
        for (int kk = 0; kk < 4; kk++) {
            uint32_t aH[4], aL[4];
            ldsm_x4(aH, SQH + a_off + kk * 32);
            ldsm_x4(aL, SQL + a_off + kk * 32);
#pragma unroll
            for (int p = 0; p < 4; p++) {
                uint32_t bo = (uint32_t)(p * 16 * ATS) + b_rowsel + kk * 32;
                uint32_t bH4[4], bL4[4];
                ldsm_x4(bH4, KH + bo);
                ldsm_x4(bL4, KL + bo);
                mma16816(s_acc[2 * p],     aH, bH4);
                mma16816(s_acc[2 * p],     aL, bH4);
                mma16816(s_acc[2 * p],     aH, bL4);
                mma16816(s_acc[2 * p + 1], aH, bH4 + 2);
                mma16816(s_acc[2 * p + 1], aL, bH4 + 2);
                mma16816(s_acc[2 * p + 1], aH, bL4 + 2);
            }
        }

#pragma unroll
        for (int j = 0; j < 8; j++)
#pragma unroll
            for (int v = 0; v < 4; v++) s_acc[j][v] *= scale;

        if (t0 + 63 > s0 + warpM) {
            const int rg0 = s0 + warpM + (lane >> 2);
#pragma unroll
            for (int nj = 0; nj < 8; nj++) {
                const int cg = t0 + nj * 8 + (lane & 3) * 2;
#pragma unroll
                for (int e = 0; e < 2; e++) {
                    if (cg + e > rg0) s_acc[nj][e] = -1e30f;
                    if (cg + e > rg0 + 8) s_acc[nj][2 + e] = -1e30f;
                }
            }
        }

        float mx0 = -1e30f, mx1 = -1e30f;
#pragma unroll
        for (int nj = 0; nj < 8; nj++) {
            mx0 = fmaxf(mx0, fmaxf(s_acc[nj][0], s_acc[nj][1]));
            mx1 = fmaxf(mx1, fmaxf(s_acc[nj][2], s_acc[nj][3]));
        }
        mx0 = fmaxf(mx0, __shfl_xor_sync(0xffffffffu, mx0, 1));
        mx0 = fmaxf(mx0, __shfl_xor_sync(0xffffffffu, mx0, 2));
        mx1 = fmaxf(mx1, __shfl_xor_sync(0xffffffffu, mx1, 1));
        mx1 = fmaxf(mx1, __shfl_xor_sync(0xffffffffu, mx1, 2));
        const float M0 = fmaxf(m0, mx0), M1 = fmaxf(m1, mx1);
        const float corr0 = __expf(m0 - M0), corr1 = __expf(m1 - M1);
        m0 = M0; m1 = M1;

        float rs0 = 0.f, rs1 = 0.f;
#pragma unroll
        for (int nj = 0; nj < 8; nj++) {
            s_acc[nj][0] = __expf(s_acc[nj][0] - M0);
            s_acc[nj][1] = __expf(s_acc[nj][1] - M0);
            s_acc[nj][2] = __expf(s_acc[nj][2] - M1);
            s_acc[nj][3] = __expf(s_acc[nj][3] - M1);
            rs0 += s_acc[nj][0] + s_acc[nj][1];
            rs1 += s_acc[nj][2] + s_acc[nj][3];
        }
        rs0 += __shfl_xor_sync(0xffffffffu, rs0, 1);
        rs0 += __shfl_xor_sync(0xffffffffu, rs0, 2);
        rs1 += __shfl_xor_sync(0xffffffffu, rs1, 1);
        rs1 += __shfl_xor_sync(0xffffffffu, rs1, 2);
        l0 = l0 * corr0 + rs0;
        l1 = l1 * corr1 + rs1;

#pragma unroll
        for (int j = 0; j < 8; j++) {
            o[j][0] *= corr0; o[j][1] *= corr0;
            o[j][2] *= corr1; o[j][3] *= corr1;
        }

#pragma unroll
        for (int kt = 0; kt < 4; kt++) {
            uint32_t pH[4], pL[4];
            split_pair(s_acc[2 * kt][0],     s_acc[2 * kt][1],     pH[0], pL[0]);
            split_pair(s_acc[2 * kt][2],     s_acc[2 * kt][3],     pH[1], pL[1]);
            split_pair(s_acc[2 * kt + 1][0], s_acc[2 * kt + 1][1], pH[2], pL[2]);
            split_pair(s_acc[2 * kt + 1][2], s_acc[2 * kt + 1][3], pH[3], pL[3]);
#pragma unroll
            for (int p = 0; p < 4; p++) {
                uint32_t vo = (uint32_t)(p * 16 * ATS) + b_rowsel + kt * 32;
                uint32_t vH4[4], vL4[4];
                ldsm_x4(vH4, VH + vo);
                ldsm_x4(vL4, VL + vo);
                mma16816(o[2 * p],     pH, vH4);
                mma16816(o[2 * p],     pL, vH4);
                mma16816(o[2 * p],     pH, vL4);
                mma16816(o[2 * p + 1], pH, vH4 + 2);
                mma16816(o[2 * p + 1], pL, vH4 + 2);
                mma16816(o[2 * p + 1], pH, vL4 + 2);
            }
        }
        __syncthreads();
    }

    const float inv0 = 1.0f / l0, inv1 = 1.0f / l1;
    const int r0 = s0 + warpM + (lane >> 2);
    const int r1 = r0 + 8;
    const int cb = h * 64 + (lane & 3) * 2;
#pragma unroll
    for (int dj = 0; dj < 8; dj++) {
        const int col = cb + dj * 8;
        uint32_t hh, ll;
        split_pair(o[dj][0] * inv0, o[dj][1] * inv0, hh, ll);
        *reinterpret_cast<uint32_t*>(&g_ch[(size_t)r0 * DOUT + col]) = hh;
        *reinterpret_cast<uint32_t*>(&g_cl[(size_t)r0 * DOUT + col]) = ll;
        split_pair(o[dj][2] * inv1, o[dj][3] * inv1, hh, ll);
        *reinterpret_cast<uint32_t*>(&g_ch[(size_t)r1 * DOUT + col]) = hh;
        *reinterpret_cast<uint32_t*>(&g_cl[(size_t)r1 * DOUT + col]) = ll;
    }
}

// ---------------- launch ----------------
extern "C" void kernel_launch(void* const* d_in, const int* in_sizes, int n_in,
                              void* d_out, int out_size)
{
    const float* x    = (const float*)d_in[0];
    const float* cosb = (const float*)d_in[2];
    const float* sinb = (const float*)d_in[3];
    const float* Wq   = (const float*)d_in[4];
    const float* Wk   = (const float*)d_in[5];
    const float* Wv   = (const float*)d_in[6];
    const float* Wo   = (const float*)d_in[7];
    const float* qw   = (const float*)d_in[8];
    const float* kw   = (const float*)d_in[9];
    float* out = (float*)d_out;

    (void)in_sizes; (void)n_in; (void)out_size;

    cudaFuncSetAttribute(gemm_q_kernel,  cudaFuncAttributeMaxDynamicSharedMemorySize, GEMM_SMEM);
    cudaFuncSetAttribute(gemm_kv_kernel, cudaFuncAttributeMaxDynamicSharedMemorySize, GEMM_SMEM);
    cudaFuncSetAttribute(gemm_o_kernel,  cudaFuncAttributeMaxDynamicSharedMemorySize, GEMM_SMEM);
    cudaFuncSetAttribute(attn_kernel,    cudaFuncAttributeMaxDynamicSharedMemorySize, ATT_SMEM);

    xconv_kernel<<<(SLEN * DIN) / 256, 256>>>(x);
    wconv_q<<<dim3(DOUT / 32, DIN / 32), dim3(32, 8)>>>(Wq);
    wconv_k<<<dim3(KVD / 32, DIN / 32), dim3(32, 8)>>>(Wk);
    wconv_v<<<dim3(KVD / 32, DIN / 32), dim3(32, 8)>>>(Wv);
    wconv_o<<<dim3(DIN / 32, DOUT / 32), dim3(32, 8)>>>(Wo);

    gemm_q_kernel<<<dim3(DOUT / 128, SLEN / 128), 256, GEMM_SMEM>>>();
    gemm_kv_kernel<<<dim3(KVD / 128, SLEN / 128, 2), 256, GEMM_SMEM>>>();

    normrope_kernel<<<dim3(SLEN, 40), 64>>>(cosb, sinb, qw, kw);
    vsplit_kernel<<<dim3(SLEN / 32, 2, NKV), dim3(32, 8)>>>();

    attn_kernel<<<dim3(NH, 16), 256, ATT_SMEM>>>();

    gemm_o_kernel<<<dim3(DIN / 128, SLEN / 128), 256, GEMM_SMEM>>>(out);
}